// round 12
// baseline (speedup 1.0000x reference)
#include <cuda_runtime.h>
#include <cuda_bf16.h>
#include <cuda_fp16.h>
#include <math.h>

#define NN 50000
#define NE 800000
#define CDIM 128
#define NLAYER 4
#define NCLASS 40

// ---------------- scratch (device globals; no allocation allowed) ----------------
__device__ int   g_is64;
__device__ int   g_deg[NN];
__device__ int   g_fill[NN];
__device__ int   g_rowptr[NN + 1];
__device__ float g_dinv[NN];
__device__ int   g_bsum[64];
__device__ __align__(16) int2 g_cew[NE];                    // (src, bitcast ew) per edge
__device__ __align__(16) unsigned g_hWh[(size_t)NN * 64];   // hW rows as half2 (128 halves/row)
__device__ __align__(16) unsigned g_H16[(size_t)NLAYER * NN * 64];  // H as half2
__device__ __align__(16) float g_scores[(size_t)NN * NLAYER];
// pre-split weights: slot 0..3 = convW layers, slot 4 = W_att; [n][k] bf16x2 u32
__device__ __align__(16) unsigned g_Bh[5 * 128 * 64];
__device__ __align__(16) unsigned g_Bl[5 * 128 * 64];

// ---------------- helpers ----------------
__device__ __forceinline__ unsigned short bf_hi(float x) {
    return __bfloat16_as_ushort(__float2bfloat16(x));
}
__device__ __forceinline__ void split2(float x0, float x1, unsigned& hi, unsigned& lo) {
    unsigned short h0 = bf_hi(x0), h1 = bf_hi(x1);
    float r0 = x0 - __bfloat162float(__ushort_as_bfloat16(h0));
    float r1 = x1 - __bfloat162float(__ushort_as_bfloat16(h1));
    unsigned short l0 = bf_hi(r0), l1 = bf_hi(r1);
    hi = ((unsigned)h1 << 16) | h0;
    lo = ((unsigned)l1 << 16) | l0;
}
__device__ __forceinline__ void mma16816(float& c0, float& c1, float& c2, float& c3,
                                         unsigned a0, unsigned a1, unsigned a2, unsigned a3,
                                         unsigned b0, unsigned b1) {
    asm volatile("mma.sync.aligned.m16n8k16.row.col.f32.bf16.bf16.f32 "
                 "{%0,%1,%2,%3}, {%4,%5,%6,%7}, {%8,%9}, {%0,%1,%2,%3};"
                 : "+f"(c0), "+f"(c1), "+f"(c2), "+f"(c3)
                 : "r"(a0), "r"(a1), "r"(a2), "r"(a3), "r"(b0), "r"(b1));
}
__device__ __forceinline__ unsigned smem_u32(const void* p) {
    unsigned a;
    asm("{ .reg .u64 t; cvta.to.shared.u64 t, %1; cvt.u32.u64 %0, t; }" : "=r"(a) : "l"(p));
    return a;
}
__device__ __forceinline__ void ldsm_x4(unsigned& r0, unsigned& r1, unsigned& r2, unsigned& r3,
                                        unsigned addr) {
    asm volatile("ldmatrix.sync.aligned.m8n8.x4.shared.b16 {%0,%1,%2,%3}, [%4];"
                 : "=r"(r0), "=r"(r1), "=r"(r2), "=r"(r3) : "r"(addr));
}

// ---------------- edge accessors ----------------
__device__ __forceinline__ int edge_src(const void* ei, int e) {
    return g_is64 ? (int)((const long long*)ei)[e] : ((const int*)ei)[e];
}
__device__ __forceinline__ int edge_dst(const void* ei, int e) {
    return g_is64 ? (int)((const long long*)ei)[NE + e] : ((const int*)ei)[NE + e];
}

// ---------------- CSR build ----------------
__global__ void zero_kernel(const void* ei) {
    int i = blockIdx.x * blockDim.x + threadIdx.x;
    if (i == 0) {
        const long long* p = (const long long*)ei;
        int ok = 1;
        for (int k = 0; k < 8; ++k) {
            long long v = p[k];
            if (v < 0 || v >= NN) ok = 0;
        }
        g_is64 = ok;
    }
    if (i < NN) { g_deg[i] = 0; g_fill[i] = 0; }
}
__global__ void hist_kernel(const void* __restrict__ ei) {
    int e = blockIdx.x * blockDim.x + threadIdx.x;
    if (e < NE) {
        int d = edge_dst(ei, e);
        if ((unsigned)d < NN) atomicAdd(&g_deg[d], 1);
    }
}
__global__ __launch_bounds__(1024) void scan1_kernel() {
    __shared__ int wsum[32];
    int b = blockIdx.x, t = threadIdx.x;
    int i = b * 1024 + t;
    int lane = t & 31, wid = t >> 5;
    int v = (i < NN) ? g_deg[i] : 0;
    if (i < NN) g_dinv[i] = rsqrtf(1.0f + (float)v);
    int inc = v;
#pragma unroll
    for (int o = 1; o < 32; o <<= 1) {
        int u = __shfl_up_sync(0xffffffffu, inc, o);
        if (lane >= o) inc += u;
    }
    if (lane == 31) wsum[wid] = inc;
    __syncthreads();
    if (wid == 0) {
        int s = wsum[lane];
#pragma unroll
        for (int o = 1; o < 32; o <<= 1) {
            int u = __shfl_up_sync(0xffffffffu, s, o);
            if (lane >= o) s += u;
        }
        wsum[lane] = s;
    }
    __syncthreads();
    int incl = inc + (wid ? wsum[wid - 1] : 0);
    if (i < NN) g_rowptr[i + 1] = incl;
    if (t == 1023) g_bsum[b] = incl;
}
__global__ __launch_bounds__(1024) void scan3_kernel() {
    __shared__ int sm[64];
    int b = blockIdx.x, t = threadIdx.x;
    if (t < 64) sm[t] = (t < 49) ? g_bsum[t] : 0;
    __syncthreads();
    for (int o = 1; o < 64; o <<= 1) {
        int u = (t < 64 && t >= o) ? sm[t - o] : 0;
        __syncthreads();
        if (t < 64) sm[t] += u;
        __syncthreads();
    }
    int add = (b == 0) ? 0 : sm[b - 1];
    int i = b * 1024 + t;
    if (i < NN) g_rowptr[i + 1] += add;
    if (i == 0) g_rowptr[0] = 0;
}
__global__ void scatter_kernel(const void* __restrict__ ei) {
    int e = blockIdx.x * blockDim.x + threadIdx.x;
    if (e < NE) {
        int s = edge_src(ei, e);
        int d = edge_dst(ei, e);
        if ((unsigned)s < NN && (unsigned)d < NN) {
            int pos = g_rowptr[d] + atomicAdd(&g_fill[d], 1);
            g_cew[pos] = make_int2(s, __float_as_int(g_dinv[s] * g_dinv[d]));
        }
    }
}

// ---------------- B prep: all 5 weight matrices at once ----------------
__global__ void bprep_kernel(const float* __restrict__ convW, const float* __restrict__ Watt) {
    int idx = blockIdx.x * 256 + threadIdx.x;
    if (idx >= 5 * 128 * 64) return;
    int slot = idx >> 13;          // 0..4
    int r = idx & 8191;
    int n = r >> 6, q = r & 63, k = q * 2;
    const float* B = (slot < 4) ? (convW + (size_t)slot * 128 * 128) : Watt;
    float x0 = B[(size_t)k * 128 + n];
    float x1 = B[(size_t)(k + 1) * 128 + n];
    unsigned hi, lo;
    split2(x0, x1, hi, lo);
    g_Bh[slot * 8192 + n * 64 + q] = hi;
    g_Bl[slot * 8192 + n * 64 + q] = lo;
}

// ---------------- tensor-core GEMM (split bf16), dual-role launch ----------------
// Blocks [0, nconv): conv  A @ convW[conv_slot] -> g_hWh (fp16)
// Blocks [nconv, grid): att  tanh(A @ W_att) . avec -> g_scores[:, att_layer]
// A = (a_layer < 0 ? x fp32 : g_H16[a_layer] fp16)
__global__ __launch_bounds__(256, 2) void gemm_kernel(const float* __restrict__ x,
                                                      const float* __restrict__ avec,
                                                      int a_layer, int conv_slot,
                                                      int att_layer, int nconv) {
    __shared__ unsigned short Ah[128][40], Al[128][40];   // row stride 80B = 16*5
    __shared__ unsigned short Bh[128][40], Bl[128][40];
    __shared__ float red[128][2];

    bool is_att = ((int)blockIdx.x >= nconv);
    int blk = is_att ? (int)blockIdx.x - nconv : (int)blockIdx.x;
    bool a_is_x = (a_layer < 0);
    const unsigned* A16 = g_H16 + (a_is_x ? 0 : (size_t)a_layer * NN * 64);
    int slot = is_att ? 4 : conv_slot;
    const unsigned* GBh = g_Bh + slot * 8192;
    const unsigned* GBl = g_Bl + slot * 8192;

    int tid = threadIdx.x;
    int m0 = blk * 128;
    int lane = tid & 31, w = tid >> 5;
    int g = lane >> 2, t = lane & 3;
    int wm = (w & 3) * 32, wn = (w >> 2) * 64;

    int mi = lane >> 3, r8 = lane & 7;
    unsigned a_h[2], a_l[2];
#pragma unroll
    for (int s = 0; s < 2; ++s) {
        int row = wm + s * 16 + (mi & 1) * 8 + r8;
        int col = (mi >> 1) * 8;
        a_h[s] = smem_u32(&Ah[row][col]);
        a_l[s] = smem_u32(&Al[row][col]);
    }
    unsigned b_h[4], b_l[4];
#pragma unroll
    for (int jp = 0; jp < 4; ++jp) {
        int row = wn + jp * 16 + (mi >> 1) * 8 + r8;
        int col = (mi & 1) * 8;
        b_h[jp] = smem_u32(&Bh[row][col]);
        b_l[jp] = smem_u32(&Bl[row][col]);
    }

    float c[2][8][4];
#pragma unroll
    for (int s = 0; s < 2; ++s)
#pragma unroll
        for (int j = 0; j < 8; ++j)
#pragma unroll
            for (int q = 0; q < 4; ++q) c[s][j][q] = 0.f;

    // A prefetch: fp32 (x) or fp16 (H)
    float4 pf[4];
#pragma unroll
    for (int it = 0; it < 4; ++it) {
        int idx = it * 256 + tid;
        int m = idx >> 3, q = idx & 7;
        int row = m0 + m;
        pf[it] = make_float4(0.f, 0.f, 0.f, 0.f);
        if (row < NN) {
            if (a_is_x) {
                pf[it] = *(const float4*)(x + (size_t)row * 128 + q * 4);
            } else {
                uint2 u = *(const uint2*)(A16 + (size_t)row * 64 + q * 2);
                float2 f01 = __half22float2(*(__half2*)&u.x);
                float2 f23 = __half22float2(*(__half2*)&u.y);
                pf[it] = make_float4(f01.x, f01.y, f23.x, f23.y);
            }
        }
    }

    for (int kc = 0; kc < 128; kc += 32) {
#pragma unroll
        for (int it = 0; it < 4; ++it) {
            int idx = it * 256 + tid;
            int m = idx >> 3, q = idx & 7;
            unsigned h0, l0, h1, l1;
            split2(pf[it].x, pf[it].y, h0, l0);
            split2(pf[it].z, pf[it].w, h1, l1);
            *(unsigned*)&Ah[m][q * 4]     = h0;
            *(unsigned*)&Ah[m][q * 4 + 2] = h1;
            *(unsigned*)&Al[m][q * 4]     = l0;
            *(unsigned*)&Al[m][q * 4 + 2] = l1;
        }
#pragma unroll
        for (int it = 0; it < 16; ++it) {
            int idx = it * 256 + tid;
            int half = idx >> 11;
            int rr = idx & 2047;
            int n = rr >> 4, q = rr & 15;
            unsigned val = (half ? GBl : GBh)[n * 64 + (kc >> 1) + q];
            if (half) *(unsigned*)&Bl[n][q * 2] = val;
            else      *(unsigned*)&Bh[n][q * 2] = val;
        }
        __syncthreads();

        if (kc < 96) {
#pragma unroll
            for (int it = 0; it < 4; ++it) {
                int idx = it * 256 + tid;
                int m = idx >> 3, q = idx & 7;
                int row = m0 + m;
                pf[it] = make_float4(0.f, 0.f, 0.f, 0.f);
                if (row < NN) {
                    if (a_is_x) {
                        pf[it] = *(const float4*)(x + (size_t)row * 128 + kc + 32 + q * 4);
                    } else {
                        uint2 u = *(const uint2*)(A16 + (size_t)row * 64 + (kc + 32) / 2 + q * 2);
                        float2 f01 = __half22float2(*(__half2*)&u.x);
                        float2 f23 = __half22float2(*(__half2*)&u.y);
                        pf[it] = make_float4(f01.x, f01.y, f23.x, f23.y);
                    }
                }
            }
        }

#pragma unroll
        for (int ks = 0; ks < 32; ks += 16) {
            unsigned koff = ks * 2;
            unsigned ah[2][4], al[2][4];
#pragma unroll
            for (int s = 0; s < 2; ++s) {
                ldsm_x4(ah[s][0], ah[s][1], ah[s][2], ah[s][3], a_h[s] + koff);
                ldsm_x4(al[s][0], al[s][1], al[s][2], al[s][3], a_l[s] + koff);
            }
#pragma unroll
            for (int jp = 0; jp < 4; ++jp) {
                unsigned bh0, bh1, bh2, bh3, bl0, bl1, bl2, bl3;
                ldsm_x4(bh0, bh1, bh2, bh3, b_h[jp] + koff);
                ldsm_x4(bl0, bl1, bl2, bl3, b_l[jp] + koff);
#pragma unroll
                for (int s = 0; s < 2; ++s) {
                    mma16816(c[s][2 * jp][0], c[s][2 * jp][1], c[s][2 * jp][2], c[s][2 * jp][3],
                             ah[s][0], ah[s][1], ah[s][2], ah[s][3], bh0, bh1);
                    mma16816(c[s][2 * jp][0], c[s][2 * jp][1], c[s][2 * jp][2], c[s][2 * jp][3],
                             ah[s][0], ah[s][1], ah[s][2], ah[s][3], bl0, bl1);
                    mma16816(c[s][2 * jp][0], c[s][2 * jp][1], c[s][2 * jp][2], c[s][2 * jp][3],
                             al[s][0], al[s][1], al[s][2], al[s][3], bh0, bh1);
                    mma16816(c[s][2 * jp + 1][0], c[s][2 * jp + 1][1], c[s][2 * jp + 1][2], c[s][2 * jp + 1][3],
                             ah[s][0], ah[s][1], ah[s][2], ah[s][3], bh2, bh3);
                    mma16816(c[s][2 * jp + 1][0], c[s][2 * jp + 1][1], c[s][2 * jp + 1][2], c[s][2 * jp + 1][3],
                             ah[s][0], ah[s][1], ah[s][2], ah[s][3], bl2, bl3);
                    mma16816(c[s][2 * jp + 1][0], c[s][2 * jp + 1][1], c[s][2 * jp + 1][2], c[s][2 * jp + 1][3],
                             al[s][0], al[s][1], al[s][2], al[s][3], bh2, bh3);
                }
            }
        }
        __syncthreads();
    }

    if (!is_att) {
        __half2* C = (__half2*)g_hWh;
#pragma unroll
        for (int s = 0; s < 2; ++s) {
#pragma unroll
            for (int j = 0; j < 8; ++j) {
                int rr = m0 + wm + s * 16 + g;
                int n = wn + j * 8 + 2 * t;        // even
                if (rr < NN)     C[(size_t)rr * 64 + (n >> 1)]       = __floats2half2_rn(c[s][j][0], c[s][j][1]);
                if (rr + 8 < NN) C[(size_t)(rr + 8) * 64 + (n >> 1)] = __floats2half2_rn(c[s][j][2], c[s][j][3]);
            }
        }
    } else {
        float p[2][2] = {{0.f, 0.f}, {0.f, 0.f}};
#pragma unroll
        for (int j = 0; j < 8; ++j) {
            int n = wn + j * 8 + 2 * t;
            float a0 = avec[n], a1 = avec[n + 1];
#pragma unroll
            for (int s = 0; s < 2; ++s) {
                p[s][0] += tanhf(c[s][j][0]) * a0 + tanhf(c[s][j][1]) * a1;
                p[s][1] += tanhf(c[s][j][2]) * a0 + tanhf(c[s][j][3]) * a1;
            }
        }
#pragma unroll
        for (int s = 0; s < 2; ++s)
#pragma unroll
            for (int h = 0; h < 2; ++h) {
                p[s][h] += __shfl_xor_sync(0xffffffffu, p[s][h], 1);
                p[s][h] += __shfl_xor_sync(0xffffffffu, p[s][h], 2);
            }
        __syncthreads();
        if (t == 0) {
#pragma unroll
            for (int s = 0; s < 2; ++s) {
                red[wm + s * 16 + g][w >> 2]     = p[s][0];
                red[wm + s * 16 + g + 8][w >> 2] = p[s][1];
            }
        }
        __syncthreads();
        if (tid < 128) {
            int row = m0 + tid;
            if (row < NN)
                g_scores[(size_t)row * NLAYER + att_layer] = red[tid][0] + red[tid][1];
        }
    }
}

// ---------------- aggregation: one warp per dst node, fp16 in + fp16 out ----------------
__global__ __launch_bounds__(256) void agg_kernel(const float* __restrict__ convb, int l) {
    int w = (blockIdx.x * blockDim.x + threadIdx.x) >> 5;
    int lane = threadIdx.x & 31;
    if (w >= NN) return;
    const float* bias = convb + (size_t)l * CDIM;
    const uint2* hw = (const uint2*)g_hWh;
    const int2* cew = g_cew;
    float4 acc = make_float4(0.f, 0.f, 0.f, 0.f);
    int e = g_rowptr[w], e1 = g_rowptr[w + 1];

    for (; e + 3 < e1; e += 4) {
        int2 c0 = cew[e], c1 = cew[e + 1], c2 = cew[e + 2], c3 = cew[e + 3];
        uint2 u0 = hw[(size_t)c0.x * 32 + lane];
        uint2 u1 = hw[(size_t)c1.x * 32 + lane];
        uint2 u2 = hw[(size_t)c2.x * 32 + lane];
        uint2 u3 = hw[(size_t)c3.x * 32 + lane];
        float w0 = __int_as_float(c0.y), w1 = __int_as_float(c1.y);
        float w2 = __int_as_float(c2.y), w3 = __int_as_float(c3.y);
        float2 a0 = __half22float2(*(__half2*)&u0.x), b0 = __half22float2(*(__half2*)&u0.y);
        float2 a1 = __half22float2(*(__half2*)&u1.x), b1 = __half22float2(*(__half2*)&u1.y);
        float2 a2 = __half22float2(*(__half2*)&u2.x), b2 = __half22float2(*(__half2*)&u2.y);
        float2 a3 = __half22float2(*(__half2*)&u3.x), b3 = __half22float2(*(__half2*)&u3.y);
        acc.x += w0 * a0.x + w1 * a1.x + w2 * a2.x + w3 * a3.x;
        acc.y += w0 * a0.y + w1 * a1.y + w2 * a2.y + w3 * a3.y;
        acc.z += w0 * b0.x + w1 * b1.x + w2 * b2.x + w3 * b3.x;
        acc.w += w0 * b0.y + w1 * b1.y + w2 * b2.y + w3 * b3.y;
    }
    if (e + 1 < e1) {
        int2 c0 = cew[e], c1 = cew[e + 1];
        uint2 u0 = hw[(size_t)c0.x * 32 + lane];
        uint2 u1 = hw[(size_t)c1.x * 32 + lane];
        float w0 = __int_as_float(c0.y), w1 = __int_as_float(c1.y);
        float2 a0 = __half22float2(*(__half2*)&u0.x), b0 = __half22float2(*(__half2*)&u0.y);
        float2 a1 = __half22float2(*(__half2*)&u1.x), b1 = __half22float2(*(__half2*)&u1.y);
        acc.x += w0 * a0.x + w1 * a1.x;
        acc.y += w0 * a0.y + w1 * a1.y;
        acc.z += w0 * b0.x + w1 * b1.x;
        acc.w += w0 * b0.y + w1 * b1.y;
        e += 2;
    }
    if (e < e1) {
        int2 c0 = cew[e];
        uint2 u0 = hw[(size_t)c0.x * 32 + lane];
        float w0 = __int_as_float(c0.y);
        float2 a0 = __half22float2(*(__half2*)&u0.x), b0 = __half22float2(*(__half2*)&u0.y);
        acc.x += w0 * a0.x; acc.y += w0 * a0.y;
        acc.z += w0 * b0.x; acc.w += w0 * b0.y;
    }
    float di = g_dinv[w];
    float sn = di * di;
    uint2 us = hw[(size_t)w * 32 + lane];
    float2 s0 = __half22float2(*(__half2*)&us.x), s1 = __half22float2(*(__half2*)&us.y);
    const float4* b4 = (const float4*)bias;
    float4 b = b4[lane];
    float rx = fmaxf(acc.x + sn * s0.x + b.x, 0.f);
    float ry = fmaxf(acc.y + sn * s0.y + b.y, 0.f);
    float rz = fmaxf(acc.z + sn * s1.x + b.z, 0.f);
    float rw = fmaxf(acc.w + sn * s1.y + b.w, 0.f);
    __half2 h01 = __floats2half2_rn(rx, ry);
    __half2 h23 = __floats2half2_rn(rz, rw);
    uint2 o;
    o.x = *(unsigned*)&h01;
    o.y = *(unsigned*)&h23;
    ((uint2*)(g_H16 + (size_t)l * NN * 64))[(size_t)w * 32 + lane] = o;
}

// ---------------- final: softmax over layers + layer-mix (fp16 H) + out GEMM ----------------
__global__ __launch_bounds__(256) void final_kernel(const float* __restrict__ Wout,
                                                    const float* __restrict__ bout,
                                                    float* __restrict__ out) {
    __shared__ float At[128][33];
    __shared__ float Ws[128][40];
    __shared__ float sal[128][4];
    int tid = threadIdx.x;
    int m0 = blockIdx.x * 128;

    if (tid < 128) {
        int row = m0 + tid;
        float s0 = 0.f, s1 = 0.f, s2 = 0.f, s3 = 0.f;
        if (row < NN) {
            s0 = g_scores[(size_t)row * 4 + 0];
            s1 = g_scores[(size_t)row * 4 + 1];
            s2 = g_scores[(size_t)row * 4 + 2];
            s3 = g_scores[(size_t)row * 4 + 3];
        }
        float mx = fmaxf(fmaxf(s0, s1), fmaxf(s2, s3));
        float e0 = expf(s0 - mx), e1 = expf(s1 - mx), e2 = expf(s2 - mx), e3 = expf(s3 - mx);
        float inv = 1.0f / (e0 + e1 + e2 + e3);
        sal[tid][0] = e0 * inv; sal[tid][1] = e1 * inv;
        sal[tid][2] = e2 * inv; sal[tid][3] = e3 * inv;
    }
    for (int i = tid; i < 128 * 40; i += 256) Ws[i / 40][i % 40] = Wout[i];
    __syncthreads();

    float acc[4][5];
#pragma unroll
    for (int r = 0; r < 4; ++r)
#pragma unroll
        for (int j = 0; j < 5; ++j) acc[r][j] = 0.f;

    int ty = tid >> 3, tx = tid & 7;
    const size_t L32 = (size_t)NN * 64;

    for (int kc = 0; kc < 128; kc += 32) {
#pragma unroll
        for (int it = 0; it < 4; ++it) {
            int idx = it * 256 + tid;
            int m = idx >> 3, kq = idx & 7;
            int row = m0 + m;
            float4 v = make_float4(0.f, 0.f, 0.f, 0.f);
            if (row < NN) {
                size_t off = (size_t)row * 64 + (kc >> 1) + kq * 2;  // u32 index
                float a0 = sal[m][0], a1 = sal[m][1], a2 = sal[m][2], a3 = sal[m][3];
                uint2 u0 = *(const uint2*)(g_H16 + off);
                uint2 u1 = *(const uint2*)(g_H16 + off + L32);
                uint2 u2 = *(const uint2*)(g_H16 + off + 2 * L32);
                uint2 u3 = *(const uint2*)(g_H16 + off + 3 * L32);
                float2 p0 = __half22float2(*(__half2*)&u0.x), q0 = __half22float2(*(__half2*)&u0.y);
                float2 p1 = __half22float2(*(__half2*)&u1.x), q1 = __half22float2(*(__half2*)&u1.y);
                float2 p2 = __half22float2(*(__half2*)&u2.x), q2 = __half22float2(*(__half2*)&u2.y);
                float2 p3 = __half22float2(*(__half2*)&u3.x), q3 = __half22float2(*(__half2*)&u3.y);
                v.x = a0 * p0.x + a1 * p1.x + a2 * p2.x + a3 * p3.x;
                v.y = a0 * p0.y + a1 * p1.y + a2 * p2.y + a3 * p3.y;
                v.z = a0 * q0.x + a1 * q1.x + a2 * q2.x + a3 * q3.x;
                v.w = a0 * q0.y + a1 * q1.y + a2 * q2.y + a3 * q3.y;
            }
            At[m][kq * 4 + 0] = v.x; At[m][kq * 4 + 1] = v.y;
            At[m][kq * 4 + 2] = v.z; At[m][kq * 4 + 3] = v.w;
        }
        __syncthreads();
#pragma unroll
        for (int kk = 0; kk < 32; ++kk) {
            float a[4];
#pragma unroll
            for (int rr = 0; rr < 4; ++rr) a[rr] = At[ty * 4 + rr][kk];
            float b[5];
#pragma unroll
            for (int j = 0; j < 5; ++j) b[j] = Ws[kc + kk][tx * 5 + j];
#pragma unroll
            for (int rr = 0; rr < 4; ++rr)
#pragma unroll
                for (int j = 0; j < 5; ++j) acc[rr][j] += a[rr] * b[j];
        }
        __syncthreads();
    }

#pragma unroll
    for (int rr = 0; rr < 4; ++rr) {
        int row = m0 + ty * 4 + rr;
        if (row < NN) {
#pragma unroll
            for (int j = 0; j < 5; ++j) {
                int col = tx * 5 + j;
                out[(size_t)row * NCLASS + col] = acc[rr][j] + bout[col];
            }
        }
    }
}

// ---------------- launch ----------------
static const void* find_by_size(void* const* d_in, const int* in_sizes, int n_in,
                                long long want, const void* fallback) {
    for (int i = 0; i < n_in; ++i)
        if ((long long)in_sizes[i] == want) return d_in[i];
    return fallback;
}

extern "C" void kernel_launch(void* const* d_in, const int* in_sizes, int n_in,
                              void* d_out, int out_size) {
    const float* x     = (const float*)find_by_size(d_in, in_sizes, n_in, (long long)NN * CDIM, d_in[0]);
    const void*  ei    =               find_by_size(d_in, in_sizes, n_in, 2LL * NE,            d_in[1]);
    const float* convW = (const float*)find_by_size(d_in, in_sizes, n_in, (long long)NLAYER * CDIM * CDIM, d_in[2]);
    const float* convb = (const float*)find_by_size(d_in, in_sizes, n_in, (long long)NLAYER * CDIM, d_in[3]);
    const float* W_att = (const float*)find_by_size(d_in, in_sizes, n_in, (long long)CDIM * CDIM, d_in[4]);
    const float* a_att = (const float*)find_by_size(d_in, in_sizes, n_in, (long long)CDIM, d_in[5]);
    const float* W_out = (const float*)find_by_size(d_in, in_sizes, n_in, (long long)CDIM * NCLASS, d_in[6]);
    const float* b_out = (const float*)find_by_size(d_in, in_sizes, n_in, (long long)NCLASS, d_in[7]);
    float*       out   = (float*)d_out;

    zero_kernel<<<(NN + 255) / 256, 256>>>(ei);
    hist_kernel<<<(NE + 255) / 256, 256>>>(ei);
    scan1_kernel<<<49, 1024>>>();
    scan3_kernel<<<49, 1024>>>();
    scatter_kernel<<<(NE + 255) / 256, 256>>>(ei);
    bprep_kernel<<<(5 * 8192 + 255) / 256, 256>>>(convW, W_att);

    const int GB = (NN + 127) / 128;  // 391
    // layer 0: conv only (A = x, fp32)
    gemm_kernel<<<GB, 256>>>(x, a_att, -1, 0, 0, GB);
    agg_kernel<<<(NN * 32 + 255) / 256, 256>>>(convb, 0);
    // layers 1..3: fused conv(l) + att(l-1), both reading g_H16[l-1]
    for (int l = 1; l < NLAYER; ++l) {
        gemm_kernel<<<2 * GB, 256>>>(x, a_att, l - 1, l, l - 1, GB);
        agg_kernel<<<(NN * 32 + 255) / 256, 256>>>(convb, l);
    }
    // att for the last layer
    gemm_kernel<<<GB, 256>>>(x, a_att, 3, 0, 3, 0);
    final_kernel<<<GB, 256>>>(W_out, b_out, out);
}

// round 14
// speedup vs baseline: 1.0285x; 1.0285x over previous
#include <cuda_runtime.h>
#include <cuda_bf16.h>
#include <cuda_fp16.h>
#include <math.h>

#define NN 50000
#define NE 800000
#define CDIM 128
#define NLAYER 4
#define NCLASS 40

// ---------------- scratch (device globals; no allocation allowed) ----------------
__device__ int   g_is64;
__device__ int   g_deg[NN];
__device__ int   g_fill[NN];
__device__ int   g_rowptr[NN + 1];
__device__ float g_dinv[NN];
__device__ int   g_bsum[64];
__device__ __align__(16) int2 g_cew[NE];                    // (src, bitcast ew) per edge
__device__ __align__(16) unsigned g_hWh[(size_t)NN * 64];   // hW rows as half2 (128 halves/row)
__device__ __align__(16) float g_H[(size_t)NLAYER * NN * CDIM];
__device__ __align__(16) float g_scores[(size_t)NN * NLAYER];
// pre-split weights: slot 0..3 = convW layers, slot 4 = W_att; [n][k] bf16x2 u32
__device__ __align__(16) unsigned g_Bh[5 * 128 * 64];
__device__ __align__(16) unsigned g_Bl[5 * 128 * 64];

// ---------------- helpers ----------------
__device__ __forceinline__ unsigned short bf_hi(float x) {
    return __bfloat16_as_ushort(__float2bfloat16(x));
}
__device__ __forceinline__ void split2(float x0, float x1, unsigned& hi, unsigned& lo) {
    unsigned short h0 = bf_hi(x0), h1 = bf_hi(x1);
    float r0 = x0 - __bfloat162float(__ushort_as_bfloat16(h0));
    float r1 = x1 - __bfloat162float(__ushort_as_bfloat16(h1));
    unsigned short l0 = bf_hi(r0), l1 = bf_hi(r1);
    hi = ((unsigned)h1 << 16) | h0;
    lo = ((unsigned)l1 << 16) | l0;
}
__device__ __forceinline__ void mma16816(float& c0, float& c1, float& c2, float& c3,
                                         unsigned a0, unsigned a1, unsigned a2, unsigned a3,
                                         unsigned b0, unsigned b1) {
    asm volatile("mma.sync.aligned.m16n8k16.row.col.f32.bf16.bf16.f32 "
                 "{%0,%1,%2,%3}, {%4,%5,%6,%7}, {%8,%9}, {%0,%1,%2,%3};"
                 : "+f"(c0), "+f"(c1), "+f"(c2), "+f"(c3)
                 : "r"(a0), "r"(a1), "r"(a2), "r"(a3), "r"(b0), "r"(b1));
}
__device__ __forceinline__ unsigned smem_u32(const void* p) {
    unsigned a;
    asm("{ .reg .u64 t; cvta.to.shared.u64 t, %1; cvt.u32.u64 %0, t; }" : "=r"(a) : "l"(p));
    return a;
}
__device__ __forceinline__ void ldsm_x4(unsigned& r0, unsigned& r1, unsigned& r2, unsigned& r3,
                                        unsigned addr) {
    asm volatile("ldmatrix.sync.aligned.m8n8.x4.shared.b16 {%0,%1,%2,%3}, [%4];"
                 : "=r"(r0), "=r"(r1), "=r"(r2), "=r"(r3) : "r"(addr));
}

// ---------------- edge accessors ----------------
__device__ __forceinline__ int edge_src(const void* ei, int e) {
    return g_is64 ? (int)((const long long*)ei)[e] : ((const int*)ei)[e];
}
__device__ __forceinline__ int edge_dst(const void* ei, int e) {
    return g_is64 ? (int)((const long long*)ei)[NE + e] : ((const int*)ei)[NE + e];
}

// ---------------- CSR build ----------------
__global__ void zero_kernel(const void* ei) {
    int i = blockIdx.x * blockDim.x + threadIdx.x;
    if (i == 0) {
        const long long* p = (const long long*)ei;
        int ok = 1;
        for (int k = 0; k < 8; ++k) {
            long long v = p[k];
            if (v < 0 || v >= NN) ok = 0;
        }
        g_is64 = ok;
    }
    if (i < NN) { g_deg[i] = 0; g_fill[i] = 0; }
}
__global__ void hist_kernel(const void* __restrict__ ei) {
    int e = blockIdx.x * blockDim.x + threadIdx.x;
    if (e < NE) {
        int d = edge_dst(ei, e);
        if ((unsigned)d < NN) atomicAdd(&g_deg[d], 1);
    }
}
__global__ __launch_bounds__(1024) void scan1_kernel() {
    __shared__ int wsum[32];
    int b = blockIdx.x, t = threadIdx.x;
    int i = b * 1024 + t;
    int lane = t & 31, wid = t >> 5;
    int v = (i < NN) ? g_deg[i] : 0;
    if (i < NN) g_dinv[i] = rsqrtf(1.0f + (float)v);
    int inc = v;
#pragma unroll
    for (int o = 1; o < 32; o <<= 1) {
        int u = __shfl_up_sync(0xffffffffu, inc, o);
        if (lane >= o) inc += u;
    }
    if (lane == 31) wsum[wid] = inc;
    __syncthreads();
    if (wid == 0) {
        int s = wsum[lane];
#pragma unroll
        for (int o = 1; o < 32; o <<= 1) {
            int u = __shfl_up_sync(0xffffffffu, s, o);
            if (lane >= o) s += u;
        }
        wsum[lane] = s;
    }
    __syncthreads();
    int incl = inc + (wid ? wsum[wid - 1] : 0);
    if (i < NN) g_rowptr[i + 1] = incl;
    if (t == 1023) g_bsum[b] = incl;
}
__global__ __launch_bounds__(1024) void scan3_kernel() {
    __shared__ int sm[64];
    int b = blockIdx.x, t = threadIdx.x;
    if (t < 64) sm[t] = (t < 49) ? g_bsum[t] : 0;
    __syncthreads();
    for (int o = 1; o < 64; o <<= 1) {
        int u = (t < 64 && t >= o) ? sm[t - o] : 0;
        __syncthreads();
        if (t < 64) sm[t] += u;
        __syncthreads();
    }
    int add = (b == 0) ? 0 : sm[b - 1];
    int i = b * 1024 + t;
    if (i < NN) g_rowptr[i + 1] += add;
    if (i == 0) g_rowptr[0] = 0;
}
__global__ void scatter_kernel(const void* __restrict__ ei) {
    int e = blockIdx.x * blockDim.x + threadIdx.x;
    if (e < NE) {
        int s = edge_src(ei, e);
        int d = edge_dst(ei, e);
        if ((unsigned)s < NN && (unsigned)d < NN) {
            int pos = g_rowptr[d] + atomicAdd(&g_fill[d], 1);
            g_cew[pos] = make_int2(s, __float_as_int(g_dinv[s] * g_dinv[d]));
        }
    }
}

// ---------------- B prep: all 5 weight matrices at once ----------------
__global__ void bprep_kernel(const float* __restrict__ convW, const float* __restrict__ Watt) {
    int idx = blockIdx.x * 256 + threadIdx.x;
    if (idx >= 5 * 128 * 64) return;
    int slot = idx >> 13;          // 0..4
    int r = idx & 8191;
    int n = r >> 6, q = r & 63, k = q * 2;
    const float* B = (slot < 4) ? (convW + (size_t)slot * 128 * 128) : Watt;
    float x0 = B[(size_t)k * 128 + n];
    float x1 = B[(size_t)(k + 1) * 128 + n];
    unsigned hi, lo;
    split2(x0, x1, hi, lo);
    g_Bh[slot * 8192 + n * 64 + q] = hi;
    g_Bl[slot * 8192 + n * 64 + q] = lo;
}

// ---------------- tensor-core GEMM (split bf16) ----------------
// ATT==0: A = (a_layer < 0 ? x : g_H[a_layer]) @ convW[conv_slot] -> g_hWh (fp16)
// ATT==1: A = g_H[a_layer]; tanh(A @ W_att) . avec -> g_scores[:, att_layer]
template<int ATT>
__global__ __launch_bounds__(256, 2) void gemm_kernel(const float* __restrict__ x,
                                                      const float* __restrict__ avec,
                                                      int a_layer, int conv_slot,
                                                      int att_layer) {
    __shared__ unsigned short Ah[128][40], Al[128][40];   // row stride 80B = 16*5
    __shared__ unsigned short Bh[128][40], Bl[128][40];
    __shared__ float red[128][2];

    const float* A = (a_layer < 0) ? x : (g_H + (size_t)a_layer * NN * CDIM);
    int slot = ATT ? 4 : conv_slot;
    const unsigned* GBh = g_Bh + slot * 8192;
    const unsigned* GBl = g_Bl + slot * 8192;

    int tid = threadIdx.x;
    int m0 = blockIdx.x * 128;
    int lane = tid & 31, w = tid >> 5;
    int g = lane >> 2, t = lane & 3;
    int wm = (w & 3) * 32, wn = (w >> 2) * 64;

    int mi = lane >> 3, r8 = lane & 7;
    unsigned a_h[2], a_l[2];
#pragma unroll
    for (int s = 0; s < 2; ++s) {
        int row = wm + s * 16 + (mi & 1) * 8 + r8;
        int col = (mi >> 1) * 8;
        a_h[s] = smem_u32(&Ah[row][col]);
        a_l[s] = smem_u32(&Al[row][col]);
    }
    unsigned b_h[4], b_l[4];
#pragma unroll
    for (int jp = 0; jp < 4; ++jp) {
        int row = wn + jp * 16 + (mi >> 1) * 8 + r8;
        int col = (mi & 1) * 8;
        b_h[jp] = smem_u32(&Bh[row][col]);
        b_l[jp] = smem_u32(&Bl[row][col]);
    }

    float c[2][8][4];
#pragma unroll
    for (int s = 0; s < 2; ++s)
#pragma unroll
        for (int j = 0; j < 8; ++j)
#pragma unroll
            for (int q = 0; q < 4; ++q) c[s][j][q] = 0.f;

    float4 pf[4];
#pragma unroll
    for (int it = 0; it < 4; ++it) {
        int idx = it * 256 + tid;
        int m = idx >> 3, q = idx & 7;
        int row = m0 + m;
        pf[it] = make_float4(0.f, 0.f, 0.f, 0.f);
        if (row < NN) pf[it] = *(const float4*)(A + (size_t)row * 128 + q * 4);
    }

    for (int kc = 0; kc < 128; kc += 32) {
#pragma unroll
        for (int it = 0; it < 4; ++it) {
            int idx = it * 256 + tid;
            int m = idx >> 3, q = idx & 7;
            unsigned h0, l0, h1, l1;
            split2(pf[it].x, pf[it].y, h0, l0);
            split2(pf[it].z, pf[it].w, h1, l1);
            *(unsigned*)&Ah[m][q * 4]     = h0;
            *(unsigned*)&Ah[m][q * 4 + 2] = h1;
            *(unsigned*)&Al[m][q * 4]     = l0;
            *(unsigned*)&Al[m][q * 4 + 2] = l1;
        }
#pragma unroll
        for (int it = 0; it < 16; ++it) {
            int idx = it * 256 + tid;
            int half = idx >> 11;
            int rr = idx & 2047;
            int n = rr >> 4, q = rr & 15;
            unsigned val = (half ? GBl : GBh)[n * 64 + (kc >> 1) + q];
            if (half) *(unsigned*)&Bl[n][q * 2] = val;
            else      *(unsigned*)&Bh[n][q * 2] = val;
        }
        __syncthreads();

        if (kc < 96) {
#pragma unroll
            for (int it = 0; it < 4; ++it) {
                int idx = it * 256 + tid;
                int m = idx >> 3, q = idx & 7;
                int row = m0 + m;
                pf[it] = make_float4(0.f, 0.f, 0.f, 0.f);
                if (row < NN) pf[it] = *(const float4*)(A + (size_t)row * 128 + kc + 32 + q * 4);
            }
        }

#pragma unroll
        for (int ks = 0; ks < 32; ks += 16) {
            unsigned koff = ks * 2;
            unsigned ah[2][4], al[2][4];
#pragma unroll
            for (int s = 0; s < 2; ++s) {
                ldsm_x4(ah[s][0], ah[s][1], ah[s][2], ah[s][3], a_h[s] + koff);
                ldsm_x4(al[s][0], al[s][1], al[s][2], al[s][3], a_l[s] + koff);
            }
#pragma unroll
            for (int jp = 0; jp < 4; ++jp) {
                unsigned bh0, bh1, bh2, bh3, bl0, bl1, bl2, bl3;
                ldsm_x4(bh0, bh1, bh2, bh3, b_h[jp] + koff);
                ldsm_x4(bl0, bl1, bl2, bl3, b_l[jp] + koff);
#pragma unroll
                for (int s = 0; s < 2; ++s) {
                    mma16816(c[s][2 * jp][0], c[s][2 * jp][1], c[s][2 * jp][2], c[s][2 * jp][3],
                             ah[s][0], ah[s][1], ah[s][2], ah[s][3], bh0, bh1);
                    mma16816(c[s][2 * jp][0], c[s][2 * jp][1], c[s][2 * jp][2], c[s][2 * jp][3],
                             ah[s][0], ah[s][1], ah[s][2], ah[s][3], bl0, bl1);
                    mma16816(c[s][2 * jp][0], c[s][2 * jp][1], c[s][2 * jp][2], c[s][2 * jp][3],
                             al[s][0], al[s][1], al[s][2], al[s][3], bh0, bh1);
                    mma16816(c[s][2 * jp + 1][0], c[s][2 * jp + 1][1], c[s][2 * jp + 1][2], c[s][2 * jp + 1][3],
                             ah[s][0], ah[s][1], ah[s][2], ah[s][3], bh2, bh3);
                    mma16816(c[s][2 * jp + 1][0], c[s][2 * jp + 1][1], c[s][2 * jp + 1][2], c[s][2 * jp + 1][3],
                             ah[s][0], ah[s][1], ah[s][2], ah[s][3], bl2, bl3);
                    mma16816(c[s][2 * jp + 1][0], c[s][2 * jp + 1][1], c[s][2 * jp + 1][2], c[s][2 * jp + 1][3],
                             al[s][0], al[s][1], al[s][2], al[s][3], bh2, bh3);
                }
            }
        }
        __syncthreads();
    }

    if (ATT == 0) {
        __half2* C = (__half2*)g_hWh;
#pragma unroll
        for (int s = 0; s < 2; ++s) {
#pragma unroll
            for (int j = 0; j < 8; ++j) {
                int rr = m0 + wm + s * 16 + g;
                int n = wn + j * 8 + 2 * t;        // even
                if (rr < NN)     C[(size_t)rr * 64 + (n >> 1)]       = __floats2half2_rn(c[s][j][0], c[s][j][1]);
                if (rr + 8 < NN) C[(size_t)(rr + 8) * 64 + (n >> 1)] = __floats2half2_rn(c[s][j][2], c[s][j][3]);
            }
        }
    } else {
        float p[2][2] = {{0.f, 0.f}, {0.f, 0.f}};
#pragma unroll
        for (int j = 0; j < 8; ++j) {
            int n = wn + j * 8 + 2 * t;
            float a0 = avec[n], a1 = avec[n + 1];
#pragma unroll
            for (int s = 0; s < 2; ++s) {
                p[s][0] += tanhf(c[s][j][0]) * a0 + tanhf(c[s][j][1]) * a1;
                p[s][1] += tanhf(c[s][j][2]) * a0 + tanhf(c[s][j][3]) * a1;
            }
        }
#pragma unroll
        for (int s = 0; s < 2; ++s)
#pragma unroll
            for (int h = 0; h < 2; ++h) {
                p[s][h] += __shfl_xor_sync(0xffffffffu, p[s][h], 1);
                p[s][h] += __shfl_xor_sync(0xffffffffu, p[s][h], 2);
            }
        __syncthreads();
        if (t == 0) {
#pragma unroll
            for (int s = 0; s < 2; ++s) {
                red[wm + s * 16 + g][w >> 2]     = p[s][0];
                red[wm + s * 16 + g + 8][w >> 2] = p[s][1];
            }
        }
        __syncthreads();
        if (tid < 128) {
            int row = m0 + tid;
            if (row < NN)
                g_scores[(size_t)row * NLAYER + att_layer] = red[tid][0] + red[tid][1];
        }
    }
}

// ---------------- aggregation: one warp per dst node, fp16 gather, 4-edge MLP ----------------
__global__ __launch_bounds__(256) void agg_kernel(const float* __restrict__ convb, int l) {
    int w = (blockIdx.x * blockDim.x + threadIdx.x) >> 5;
    int lane = threadIdx.x & 31;
    if (w >= NN) return;
    const float* bias = convb + (size_t)l * CDIM;
    const uint2* hw = (const uint2*)g_hWh;   // 4 halves per uint2, 32 per row
    const int2* cew = g_cew;
    float4 acc = make_float4(0.f, 0.f, 0.f, 0.f);
    int e = g_rowptr[w], e1 = g_rowptr[w + 1];

    for (; e + 3 < e1; e += 4) {
        int2 c0 = cew[e], c1 = cew[e + 1], c2 = cew[e + 2], c3 = cew[e + 3];
        uint2 u0 = hw[(size_t)c0.x * 32 + lane];
        uint2 u1 = hw[(size_t)c1.x * 32 + lane];
        uint2 u2 = hw[(size_t)c2.x * 32 + lane];
        uint2 u3 = hw[(size_t)c3.x * 32 + lane];
        float w0 = __int_as_float(c0.y), w1 = __int_as_float(c1.y);
        float w2 = __int_as_float(c2.y), w3 = __int_as_float(c3.y);
        float2 a0 = __half22float2(*(__half2*)&u0.x), b0 = __half22float2(*(__half2*)&u0.y);
        float2 a1 = __half22float2(*(__half2*)&u1.x), b1 = __half22float2(*(__half2*)&u1.y);
        float2 a2 = __half22float2(*(__half2*)&u2.x), b2 = __half22float2(*(__half2*)&u2.y);
        float2 a3 = __half22float2(*(__half2*)&u3.x), b3 = __half22float2(*(__half2*)&u3.y);
        acc.x += w0 * a0.x + w1 * a1.x + w2 * a2.x + w3 * a3.x;
        acc.y += w0 * a0.y + w1 * a1.y + w2 * a2.y + w3 * a3.y;
        acc.z += w0 * b0.x + w1 * b1.x + w2 * b2.x + w3 * b3.x;
        acc.w += w0 * b0.y + w1 * b1.y + w2 * b2.y + w3 * b3.y;
    }
    if (e + 1 < e1) {
        int2 c0 = cew[e], c1 = cew[e + 1];
        uint2 u0 = hw[(size_t)c0.x * 32 + lane];
        uint2 u1 = hw[(size_t)c1.x * 32 + lane];
        float w0 = __int_as_float(c0.y), w1 = __int_as_float(c1.y);
        float2 a0 = __half22float2(*(__half2*)&u0.x), b0 = __half22float2(*(__half2*)&u0.y);
        float2 a1 = __half22float2(*(__half2*)&u1.x), b1 = __half22float2(*(__half2*)&u1.y);
        acc.x += w0 * a0.x + w1 * a1.x;
        acc.y += w0 * a0.y + w1 * a1.y;
        acc.z += w0 * b0.x + w1 * b1.x;
        acc.w += w0 * b0.y + w1 * b1.y;
        e += 2;
    }
    if (e < e1) {
        int2 c0 = cew[e];
        uint2 u0 = hw[(size_t)c0.x * 32 + lane];
        float w0 = __int_as_float(c0.y);
        float2 a0 = __half22float2(*(__half2*)&u0.x), b0 = __half22float2(*(__half2*)&u0.y);
        acc.x += w0 * a0.x; acc.y += w0 * a0.y;
        acc.z += w0 * b0.x; acc.w += w0 * b0.y;
    }
    float di = g_dinv[w];
    float sn = di * di;
    uint2 us = hw[(size_t)w * 32 + lane];
    float2 s0 = __half22float2(*(__half2*)&us.x), s1 = __half22float2(*(__half2*)&us.y);
    const float4* b4 = (const float4*)bias;
    float4 b = b4[lane];
    float4 r;
    r.x = fmaxf(acc.x + sn * s0.x + b.x, 0.f);
    r.y = fmaxf(acc.y + sn * s0.y + b.y, 0.f);
    r.z = fmaxf(acc.z + sn * s1.x + b.z, 0.f);
    r.w = fmaxf(acc.w + sn * s1.y + b.w, 0.f);
    ((float4*)(g_H + (size_t)l * NN * CDIM))[(size_t)w * 32 + lane] = r;
}

// ---------------- final: softmax over layers + layer-mix + out GEMM ----------------
__global__ __launch_bounds__(256) void final_kernel(const float* __restrict__ Wout,
                                                    const float* __restrict__ bout,
                                                    float* __restrict__ out) {
    __shared__ float At[128][33];
    __shared__ float Ws[128][40];
    __shared__ float sal[128][4];
    int tid = threadIdx.x;
    int m0 = blockIdx.x * 128;

    if (tid < 128) {
        int row = m0 + tid;
        float s0 = 0.f, s1 = 0.f, s2 = 0.f, s3 = 0.f;
        if (row < NN) {
            s0 = g_scores[(size_t)row * 4 + 0];
            s1 = g_scores[(size_t)row * 4 + 1];
            s2 = g_scores[(size_t)row * 4 + 2];
            s3 = g_scores[(size_t)row * 4 + 3];
        }
        float mx = fmaxf(fmaxf(s0, s1), fmaxf(s2, s3));
        float e0 = expf(s0 - mx), e1 = expf(s1 - mx), e2 = expf(s2 - mx), e3 = expf(s3 - mx);
        float inv = 1.0f / (e0 + e1 + e2 + e3);
        sal[tid][0] = e0 * inv; sal[tid][1] = e1 * inv;
        sal[tid][2] = e2 * inv; sal[tid][3] = e3 * inv;
    }
    for (int i = tid; i < 128 * 40; i += 256) Ws[i / 40][i % 40] = Wout[i];
    __syncthreads();

    float acc[4][5];
#pragma unroll
    for (int r = 0; r < 4; ++r)
#pragma unroll
        for (int j = 0; j < 5; ++j) acc[r][j] = 0.f;

    int ty = tid >> 3, tx = tid & 7;
    const size_t LSTR = (size_t)NN * CDIM;

    for (int kc = 0; kc < 128; kc += 32) {
#pragma unroll
        for (int it = 0; it < 4; ++it) {
            int idx = it * 256 + tid;
            int m = idx >> 3, kq = idx & 7;
            int row = m0 + m;
            float4 v = make_float4(0.f, 0.f, 0.f, 0.f);
            if (row < NN) {
                size_t off = (size_t)row * 128 + kc + kq * 4;
                float a0 = sal[m][0], a1 = sal[m][1], a2 = sal[m][2], a3 = sal[m][3];
                float4 h0 = *(const float4*)(g_H + off);
                float4 h1 = *(const float4*)(g_H + off + LSTR);
                float4 h2 = *(const float4*)(g_H + off + 2 * LSTR);
                float4 h3 = *(const float4*)(g_H + off + 3 * LSTR);
                v.x = a0 * h0.x + a1 * h1.x + a2 * h2.x + a3 * h3.x;
                v.y = a0 * h0.y + a1 * h1.y + a2 * h2.y + a3 * h3.y;
                v.z = a0 * h0.z + a1 * h1.z + a2 * h2.z + a3 * h3.z;
                v.w = a0 * h0.w + a1 * h1.w + a2 * h2.w + a3 * h3.w;
            }
            At[m][kq * 4 + 0] = v.x; At[m][kq * 4 + 1] = v.y;
            At[m][kq * 4 + 2] = v.z; At[m][kq * 4 + 3] = v.w;
        }
        __syncthreads();
#pragma unroll
        for (int kk = 0; kk < 32; ++kk) {
            float a[4];
#pragma unroll
            for (int rr = 0; rr < 4; ++rr) a[rr] = At[ty * 4 + rr][kk];
            float b[5];
#pragma unroll
            for (int j = 0; j < 5; ++j) b[j] = Ws[kc + kk][tx * 5 + j];
#pragma unroll
            for (int rr = 0; rr < 4; ++rr)
#pragma unroll
                for (int j = 0; j < 5; ++j) acc[rr][j] += a[rr] * b[j];
        }
        __syncthreads();
    }

#pragma unroll
    for (int rr = 0; rr < 4; ++rr) {
        int row = m0 + ty * 4 + rr;
        if (row < NN) {
#pragma unroll
            for (int j = 0; j < 5; ++j) {
                int col = tx * 5 + j;
                out[(size_t)row * NCLASS + col] = acc[rr][j] + bout[col];
            }
        }
    }
}

// ---------------- launch ----------------
static const void* find_by_size(void* const* d_in, const int* in_sizes, int n_in,
                                long long want, const void* fallback) {
    for (int i = 0; i < n_in; ++i)
        if ((long long)in_sizes[i] == want) return d_in[i];
    return fallback;
}

extern "C" void kernel_launch(void* const* d_in, const int* in_sizes, int n_in,
                              void* d_out, int out_size) {
    const float* x     = (const float*)find_by_size(d_in, in_sizes, n_in, (long long)NN * CDIM, d_in[0]);
    const void*  ei    =               find_by_size(d_in, in_sizes, n_in, 2LL * NE,            d_in[1]);
    const float* convW = (const float*)find_by_size(d_in, in_sizes, n_in, (long long)NLAYER * CDIM * CDIM, d_in[2]);
    const float* convb = (const float*)find_by_size(d_in, in_sizes, n_in, (long long)NLAYER * CDIM, d_in[3]);
    const float* W_att = (const float*)find_by_size(d_in, in_sizes, n_in, (long long)CDIM * CDIM, d_in[4]);
    const float* a_att = (const float*)find_by_size(d_in, in_sizes, n_in, (long long)CDIM, d_in[5]);
    const float* W_out = (const float*)find_by_size(d_in, in_sizes, n_in, (long long)CDIM * NCLASS, d_in[6]);
    const float* b_out = (const float*)find_by_size(d_in, in_sizes, n_in, (long long)NCLASS, d_in[7]);
    float*       out   = (float*)d_out;

    // side stream + fork/join events (host resources; created per call, not freed
    // during capture; kernel_launch runs only a handful of times)
    cudaStream_t s2;
    cudaStreamCreateWithFlags(&s2, cudaStreamNonBlocking);
    cudaEvent_t evH[NLAYER], evDone;
    for (int i = 0; i < NLAYER; ++i) cudaEventCreateWithFlags(&evH[i], cudaEventDisableTiming);
    cudaEventCreateWithFlags(&evDone, cudaEventDisableTiming);

    zero_kernel<<<(NN + 255) / 256, 256>>>(ei);
    hist_kernel<<<(NE + 255) / 256, 256>>>(ei);
    scan1_kernel<<<49, 1024>>>();
    scan3_kernel<<<49, 1024>>>();
    scatter_kernel<<<(NE + 255) / 256, 256>>>(ei);
    bprep_kernel<<<(5 * 8192 + 255) / 256, 256>>>(convW, W_att);

    const int GB = (NN + 127) / 128;  // 391
    for (int l = 0; l < NLAYER; ++l) {
        // conv(l): A = (l==0 ? x : H[l-1]) -> hWh
        gemm_kernel<0><<<GB, 256>>>(x, a_att, l == 0 ? -1 : l - 1, l, 0);
        // agg(l): hWh -> H[l]
        agg_kernel<<<(NN * 32 + 255) / 256, 256>>>(convb, l);
        // fork: att(l) reads H[l], writes scores[:,l]; runs on side stream
        cudaEventRecord(evH[l], 0);
        cudaStreamWaitEvent(s2, evH[l], 0);
        gemm_kernel<1><<<GB, 256, 0, s2>>>(x, a_att, l, 0, l);
    }
    // join: final needs all scores
    cudaEventRecord(evDone, s2);
    cudaStreamWaitEvent(0, evDone, 0);
    final_kernel<<<GB, 256>>>(W_out, b_out, out);
}

// round 15
// speedup vs baseline: 1.0609x; 1.0315x over previous
#include <cuda_runtime.h>
#include <cuda_bf16.h>
#include <cuda_fp16.h>
#include <math.h>

#define NN 50000
#define NE 800000
#define CDIM 128
#define NLAYER 4
#define NCLASS 40

// ---------------- scratch (device globals; no allocation allowed) ----------------
__device__ int   g_is64;
__device__ int   g_deg[NN];
__device__ int   g_fill[NN];
__device__ int   g_rowptr[NN + 1];
__device__ float g_dinv[NN];
__device__ int   g_bsum[64];
__device__ __align__(16) int2 g_cew[NE];                    // (src, bitcast ew) per edge
__device__ __align__(16) unsigned g_hWh[(size_t)NN * 64];   // hW rows as half2 (128 halves/row)
__device__ __align__(16) float g_H[(size_t)NLAYER * NN * CDIM];
__device__ __align__(16) float g_scores[(size_t)NN * NLAYER];
// pre-split weights: slot 0..3 = convW layers, slot 4 = W_att; [n][k] bf16x2 u32
__device__ __align__(16) unsigned g_Bh[5 * 128 * 64];
__device__ __align__(16) unsigned g_Bl[5 * 128 * 64];

// ---------------- helpers ----------------
__device__ __forceinline__ unsigned short bf_hi(float x) {
    return __bfloat16_as_ushort(__float2bfloat16(x));
}
__device__ __forceinline__ void split2(float x0, float x1, unsigned& hi, unsigned& lo) {
    unsigned short h0 = bf_hi(x0), h1 = bf_hi(x1);
    float r0 = x0 - __bfloat162float(__ushort_as_bfloat16(h0));
    float r1 = x1 - __bfloat162float(__ushort_as_bfloat16(h1));
    unsigned short l0 = bf_hi(r0), l1 = bf_hi(r1);
    hi = ((unsigned)h1 << 16) | h0;
    lo = ((unsigned)l1 << 16) | l0;
}
__device__ __forceinline__ void mma16816(float& c0, float& c1, float& c2, float& c3,
                                         unsigned a0, unsigned a1, unsigned a2, unsigned a3,
                                         unsigned b0, unsigned b1) {
    asm volatile("mma.sync.aligned.m16n8k16.row.col.f32.bf16.bf16.f32 "
                 "{%0,%1,%2,%3}, {%4,%5,%6,%7}, {%8,%9}, {%0,%1,%2,%3};"
                 : "+f"(c0), "+f"(c1), "+f"(c2), "+f"(c3)
                 : "r"(a0), "r"(a1), "r"(a2), "r"(a3), "r"(b0), "r"(b1));
}
__device__ __forceinline__ unsigned smem_u32(const void* p) {
    unsigned a;
    asm("{ .reg .u64 t; cvta.to.shared.u64 t, %1; cvt.u32.u64 %0, t; }" : "=r"(a) : "l"(p));
    return a;
}
__device__ __forceinline__ void ldsm_x4(unsigned& r0, unsigned& r1, unsigned& r2, unsigned& r3,
                                        unsigned addr) {
    asm volatile("ldmatrix.sync.aligned.m8n8.x4.shared.b16 {%0,%1,%2,%3}, [%4];"
                 : "=r"(r0), "=r"(r1), "=r"(r2), "=r"(r3) : "r"(addr));
}
__device__ __forceinline__ float tanh_fast(float x) {
    float y;
    asm("tanh.approx.f32 %0, %1;" : "=f"(y) : "f"(x));
    return y;
}

// ---------------- edge accessors ----------------
__device__ __forceinline__ int edge_src(const void* ei, int e) {
    return g_is64 ? (int)((const long long*)ei)[e] : ((const int*)ei)[e];
}
__device__ __forceinline__ int edge_dst(const void* ei, int e) {
    return g_is64 ? (int)((const long long*)ei)[NE + e] : ((const int*)ei)[NE + e];
}

// ---------------- CSR build ----------------
__global__ void zero_kernel(const void* ei) {
    int i = blockIdx.x * blockDim.x + threadIdx.x;
    if (i == 0) {
        const long long* p = (const long long*)ei;
        int ok = 1;
        for (int k = 0; k < 8; ++k) {
            long long v = p[k];
            if (v < 0 || v >= NN) ok = 0;
        }
        g_is64 = ok;
    }
    if (i < NN) { g_deg[i] = 0; g_fill[i] = 0; }
}
__global__ void hist_kernel(const void* __restrict__ ei) {
    int e = blockIdx.x * blockDim.x + threadIdx.x;
    if (e < NE) {
        int d = edge_dst(ei, e);
        if ((unsigned)d < NN) atomicAdd(&g_deg[d], 1);
    }
}
__global__ __launch_bounds__(1024) void scan1_kernel() {
    __shared__ int wsum[32];
    int b = blockIdx.x, t = threadIdx.x;
    int i = b * 1024 + t;
    int lane = t & 31, wid = t >> 5;
    int v = (i < NN) ? g_deg[i] : 0;
    if (i < NN) g_dinv[i] = rsqrtf(1.0f + (float)v);
    int inc = v;
#pragma unroll
    for (int o = 1; o < 32; o <<= 1) {
        int u = __shfl_up_sync(0xffffffffu, inc, o);
        if (lane >= o) inc += u;
    }
    if (lane == 31) wsum[wid] = inc;
    __syncthreads();
    if (wid == 0) {
        int s = wsum[lane];
#pragma unroll
        for (int o = 1; o < 32; o <<= 1) {
            int u = __shfl_up_sync(0xffffffffu, s, o);
            if (lane >= o) s += u;
        }
        wsum[lane] = s;
    }
    __syncthreads();
    int incl = inc + (wid ? wsum[wid - 1] : 0);
    if (i < NN) g_rowptr[i + 1] = incl;
    if (t == 1023) g_bsum[b] = incl;
}
__global__ __launch_bounds__(1024) void scan3_kernel() {
    __shared__ int sm[64];
    int b = blockIdx.x, t = threadIdx.x;
    if (t < 64) sm[t] = (t < 49) ? g_bsum[t] : 0;
    __syncthreads();
    for (int o = 1; o < 64; o <<= 1) {
        int u = (t < 64 && t >= o) ? sm[t - o] : 0;
        __syncthreads();
        if (t < 64) sm[t] += u;
        __syncthreads();
    }
    int add = (b == 0) ? 0 : sm[b - 1];
    int i = b * 1024 + t;
    if (i < NN) g_rowptr[i + 1] += add;
    if (i == 0) g_rowptr[0] = 0;
}
__global__ void scatter_kernel(const void* __restrict__ ei) {
    int e = blockIdx.x * blockDim.x + threadIdx.x;
    if (e < NE) {
        int s = edge_src(ei, e);
        int d = edge_dst(ei, e);
        if ((unsigned)s < NN && (unsigned)d < NN) {
            int pos = g_rowptr[d] + atomicAdd(&g_fill[d], 1);
            g_cew[pos] = make_int2(s, __float_as_int(g_dinv[s] * g_dinv[d]));
        }
    }
}

// ---------------- B prep: all 5 weight matrices at once ----------------
__global__ void bprep_kernel(const float* __restrict__ convW, const float* __restrict__ Watt) {
    int idx = blockIdx.x * 256 + threadIdx.x;
    if (idx >= 5 * 128 * 64) return;
    int slot = idx >> 13;          // 0..4
    int r = idx & 8191;
    int n = r >> 6, q = r & 63, k = q * 2;
    const float* B = (slot < 4) ? (convW + (size_t)slot * 128 * 128) : Watt;
    float x0 = B[(size_t)k * 128 + n];
    float x1 = B[(size_t)(k + 1) * 128 + n];
    unsigned hi, lo;
    split2(x0, x1, hi, lo);
    g_Bh[slot * 8192 + n * 64 + q] = hi;
    g_Bl[slot * 8192 + n * 64 + q] = lo;
}

// ---------------- tensor-core GEMM (split bf16), dual-role launch ----------------
// Blocks [0, nconv): conv  A @ convW[conv_slot] -> g_hWh (fp16)
// Blocks [nconv, grid): att  tanh(A @ W_att) . avec -> g_scores[:, att_layer]
// A = (a_layer < 0 ? x : g_H[a_layer]); both roles read the SAME A.
__global__ __launch_bounds__(256, 2) void gemm_kernel(const float* __restrict__ x,
                                                      const float* __restrict__ avec,
                                                      int a_layer, int conv_slot,
                                                      int att_layer, int nconv) {
    __shared__ unsigned short Ah[128][40], Al[128][40];   // row stride 80B = 16*5
    __shared__ unsigned short Bh[128][40], Bl[128][40];
    __shared__ float red[128][2];

    bool is_att = ((int)blockIdx.x >= nconv);
    int blk = is_att ? (int)blockIdx.x - nconv : (int)blockIdx.x;
    const float* A = (a_layer < 0) ? x : (g_H + (size_t)a_layer * NN * CDIM);
    int slot = is_att ? 4 : conv_slot;
    const unsigned* GBh = g_Bh + slot * 8192;
    const unsigned* GBl = g_Bl + slot * 8192;

    int tid = threadIdx.x;
    int m0 = blk * 128;
    int lane = tid & 31, w = tid >> 5;
    int g = lane >> 2, t = lane & 3;
    int wm = (w & 3) * 32, wn = (w >> 2) * 64;

    int mi = lane >> 3, r8 = lane & 7;
    unsigned a_h[2], a_l[2];
#pragma unroll
    for (int s = 0; s < 2; ++s) {
        int row = wm + s * 16 + (mi & 1) * 8 + r8;
        int col = (mi >> 1) * 8;
        a_h[s] = smem_u32(&Ah[row][col]);
        a_l[s] = smem_u32(&Al[row][col]);
    }
    unsigned b_h[4], b_l[4];
#pragma unroll
    for (int jp = 0; jp < 4; ++jp) {
        int row = wn + jp * 16 + (mi >> 1) * 8 + r8;
        int col = (mi & 1) * 8;
        b_h[jp] = smem_u32(&Bh[row][col]);
        b_l[jp] = smem_u32(&Bl[row][col]);
    }

    float c[2][8][4];
#pragma unroll
    for (int s = 0; s < 2; ++s)
#pragma unroll
        for (int j = 0; j < 8; ++j)
#pragma unroll
            for (int q = 0; q < 4; ++q) c[s][j][q] = 0.f;

    float4 pf[4];
#pragma unroll
    for (int it = 0; it < 4; ++it) {
        int idx = it * 256 + tid;
        int m = idx >> 3, q = idx & 7;
        int row = m0 + m;
        pf[it] = make_float4(0.f, 0.f, 0.f, 0.f);
        if (row < NN) pf[it] = *(const float4*)(A + (size_t)row * 128 + q * 4);
    }

    for (int kc = 0; kc < 128; kc += 32) {
        // store prefetched A (split)
#pragma unroll
        for (int it = 0; it < 4; ++it) {
            int idx = it * 256 + tid;
            int m = idx >> 3, q = idx & 7;
            unsigned h0, l0, h1, l1;
            split2(pf[it].x, pf[it].y, h0, l0);
            split2(pf[it].z, pf[it].w, h1, l1);
            *(unsigned*)&Ah[m][q * 4]     = h0;
            *(unsigned*)&Ah[m][q * 4 + 2] = h1;
            *(unsigned*)&Al[m][q * 4]     = l0;
            *(unsigned*)&Al[m][q * 4 + 2] = l1;
        }
        // stage B chunk: vectorized uint4 (1024 uint4 = 512 hi + 512 lo)
#pragma unroll
        for (int it = 0; it < 4; ++it) {
            int idx = it * 256 + tid;
            int half = idx >> 9;               // 0: hi, 1: lo
            int rr = idx & 511;
            int n = rr >> 2, q4 = rr & 3;      // q4: uint4 within the row chunk
            uint4 val = *(const uint4*)((half ? GBl : GBh) + n * 64 + (kc >> 1) + q4 * 4);
            if (half) *(uint4*)&Bl[n][q4 * 8] = val;
            else      *(uint4*)&Bh[n][q4 * 8] = val;
        }
        __syncthreads();

        if (kc < 96) {
#pragma unroll
            for (int it = 0; it < 4; ++it) {
                int idx = it * 256 + tid;
                int m = idx >> 3, q = idx & 7;
                int row = m0 + m;
                pf[it] = make_float4(0.f, 0.f, 0.f, 0.f);
                if (row < NN) pf[it] = *(const float4*)(A + (size_t)row * 128 + kc + 32 + q * 4);
            }
        }

#pragma unroll
        for (int ks = 0; ks < 32; ks += 16) {
            unsigned koff = ks * 2;
            unsigned ah[2][4], al[2][4];
#pragma unroll
            for (int s = 0; s < 2; ++s) {
                ldsm_x4(ah[s][0], ah[s][1], ah[s][2], ah[s][3], a_h[s] + koff);
                ldsm_x4(al[s][0], al[s][1], al[s][2], al[s][3], a_l[s] + koff);
            }
#pragma unroll
            for (int jp = 0; jp < 4; ++jp) {
                unsigned bh0, bh1, bh2, bh3, bl0, bl1, bl2, bl3;
                ldsm_x4(bh0, bh1, bh2, bh3, b_h[jp] + koff);
                ldsm_x4(bl0, bl1, bl2, bl3, b_l[jp] + koff);
#pragma unroll
                for (int s = 0; s < 2; ++s) {
                    mma16816(c[s][2 * jp][0], c[s][2 * jp][1], c[s][2 * jp][2], c[s][2 * jp][3],
                             ah[s][0], ah[s][1], ah[s][2], ah[s][3], bh0, bh1);
                    mma16816(c[s][2 * jp][0], c[s][2 * jp][1], c[s][2 * jp][2], c[s][2 * jp][3],
                             ah[s][0], ah[s][1], ah[s][2], ah[s][3], bl0, bl1);
                    mma16816(c[s][2 * jp][0], c[s][2 * jp][1], c[s][2 * jp][2], c[s][2 * jp][3],
                             al[s][0], al[s][1], al[s][2], al[s][3], bh0, bh1);
                    mma16816(c[s][2 * jp + 1][0], c[s][2 * jp + 1][1], c[s][2 * jp + 1][2], c[s][2 * jp + 1][3],
                             ah[s][0], ah[s][1], ah[s][2], ah[s][3], bh2, bh3);
                    mma16816(c[s][2 * jp + 1][0], c[s][2 * jp + 1][1], c[s][2 * jp + 1][2], c[s][2 * jp + 1][3],
                             ah[s][0], ah[s][1], ah[s][2], ah[s][3], bl2, bl3);
                    mma16816(c[s][2 * jp + 1][0], c[s][2 * jp + 1][1], c[s][2 * jp + 1][2], c[s][2 * jp + 1][3],
                             al[s][0], al[s][1], al[s][2], al[s][3], bh2, bh3);
                }
            }
        }
        __syncthreads();
    }

    if (!is_att) {
        __half2* C = (__half2*)g_hWh;
#pragma unroll
        for (int s = 0; s < 2; ++s) {
#pragma unroll
            for (int j = 0; j < 8; ++j) {
                int rr = m0 + wm + s * 16 + g;
                int n = wn + j * 8 + 2 * t;        // even
                if (rr < NN)     C[(size_t)rr * 64 + (n >> 1)]       = __floats2half2_rn(c[s][j][0], c[s][j][1]);
                if (rr + 8 < NN) C[(size_t)(rr + 8) * 64 + (n >> 1)] = __floats2half2_rn(c[s][j][2], c[s][j][3]);
            }
        }
    } else {
        float p[2][2] = {{0.f, 0.f}, {0.f, 0.f}};
#pragma unroll
        for (int j = 0; j < 8; ++j) {
            int n = wn + j * 8 + 2 * t;
            float a0 = avec[n], a1 = avec[n + 1];
#pragma unroll
            for (int s = 0; s < 2; ++s) {
                p[s][0] += tanh_fast(c[s][j][0]) * a0 + tanh_fast(c[s][j][1]) * a1;
                p[s][1] += tanh_fast(c[s][j][2]) * a0 + tanh_fast(c[s][j][3]) * a1;
            }
        }
#pragma unroll
        for (int s = 0; s < 2; ++s)
#pragma unroll
            for (int h = 0; h < 2; ++h) {
                p[s][h] += __shfl_xor_sync(0xffffffffu, p[s][h], 1);
                p[s][h] += __shfl_xor_sync(0xffffffffu, p[s][h], 2);
            }
        __syncthreads();
        if (t == 0) {
#pragma unroll
            for (int s = 0; s < 2; ++s) {
                red[wm + s * 16 + g][w >> 2]     = p[s][0];
                red[wm + s * 16 + g + 8][w >> 2] = p[s][1];
            }
        }
        __syncthreads();
        if (tid < 128) {
            int row = m0 + tid;
            if (row < NN)
                g_scores[(size_t)row * NLAYER + att_layer] = red[tid][0] + red[tid][1];
        }
    }
}

// ---------------- aggregation: one warp per dst node, fp16 gather, 4-edge MLP ----------------
__global__ __launch_bounds__(256) void agg_kernel(const float* __restrict__ convb, int l) {
    int w = (blockIdx.x * blockDim.x + threadIdx.x) >> 5;
    int lane = threadIdx.x & 31;
    if (w >= NN) return;
    const float* bias = convb + (size_t)l * CDIM;
    const uint2* hw = (const uint2*)g_hWh;
    const int2* cew = g_cew;
    float4 acc = make_float4(0.f, 0.f, 0.f, 0.f);
    int e = g_rowptr[w], e1 = g_rowptr[w + 1];

    for (; e + 3 < e1; e += 4) {
        int2 c0 = cew[e], c1 = cew[e + 1], c2 = cew[e + 2], c3 = cew[e + 3];
        uint2 u0 = hw[(size_t)c0.x * 32 + lane];
        uint2 u1 = hw[(size_t)c1.x * 32 + lane];
        uint2 u2 = hw[(size_t)c2.x * 32 + lane];
        uint2 u3 = hw[(size_t)c3.x * 32 + lane];
        float w0 = __int_as_float(c0.y), w1 = __int_as_float(c1.y);
        float w2 = __int_as_float(c2.y), w3 = __int_as_float(c3.y);
        float2 a0 = __half22float2(*(__half2*)&u0.x), b0 = __half22float2(*(__half2*)&u0.y);
        float2 a1 = __half22float2(*(__half2*)&u1.x), b1 = __half22float2(*(__half2*)&u1.y);
        float2 a2 = __half22float2(*(__half2*)&u2.x), b2 = __half22float2(*(__half2*)&u2.y);
        float2 a3 = __half22float2(*(__half2*)&u3.x), b3 = __half22float2(*(__half2*)&u3.y);
        acc.x += w0 * a0.x + w1 * a1.x + w2 * a2.x + w3 * a3.x;
        acc.y += w0 * a0.y + w1 * a1.y + w2 * a2.y + w3 * a3.y;
        acc.z += w0 * b0.x + w1 * b1.x + w2 * b2.x + w3 * b3.x;
        acc.w += w0 * b0.y + w1 * b1.y + w2 * b2.y + w3 * b3.y;
    }
    if (e + 1 < e1) {
        int2 c0 = cew[e], c1 = cew[e + 1];
        uint2 u0 = hw[(size_t)c0.x * 32 + lane];
        uint2 u1 = hw[(size_t)c1.x * 32 + lane];
        float w0 = __int_as_float(c0.y), w1 = __int_as_float(c1.y);
        float2 a0 = __half22float2(*(__half2*)&u0.x), b0 = __half22float2(*(__half2*)&u0.y);
        float2 a1 = __half22float2(*(__half2*)&u1.x), b1 = __half22float2(*(__half2*)&u1.y);
        acc.x += w0 * a0.x + w1 * a1.x;
        acc.y += w0 * a0.y + w1 * a1.y;
        acc.z += w0 * b0.x + w1 * b1.x;
        acc.w += w0 * b0.y + w1 * b1.y;
        e += 2;
    }
    if (e < e1) {
        int2 c0 = cew[e];
        uint2 u0 = hw[(size_t)c0.x * 32 + lane];
        float w0 = __int_as_float(c0.y);
        float2 a0 = __half22float2(*(__half2*)&u0.x), b0 = __half22float2(*(__half2*)&u0.y);
        acc.x += w0 * a0.x; acc.y += w0 * a0.y;
        acc.z += w0 * b0.x; acc.w += w0 * b0.y;
    }
    float di = g_dinv[w];
    float sn = di * di;
    uint2 us = hw[(size_t)w * 32 + lane];
    float2 s0 = __half22float2(*(__half2*)&us.x), s1 = __half22float2(*(__half2*)&us.y);
    const float4* b4 = (const float4*)bias;
    float4 b = b4[lane];
    float4 r;
    r.x = fmaxf(acc.x + sn * s0.x + b.x, 0.f);
    r.y = fmaxf(acc.y + sn * s0.y + b.y, 0.f);
    r.z = fmaxf(acc.z + sn * s1.x + b.z, 0.f);
    r.w = fmaxf(acc.w + sn * s1.y + b.w, 0.f);
    ((float4*)(g_H + (size_t)l * NN * CDIM))[(size_t)w * 32 + lane] = r;
}

// ---------------- final: softmax over layers + layer-mix + out GEMM ----------------
__global__ __launch_bounds__(256) void final_kernel(const float* __restrict__ Wout,
                                                    const float* __restrict__ bout,
                                                    float* __restrict__ out) {
    __shared__ float At[128][33];
    __shared__ float Ws[128][40];
    __shared__ float sal[128][4];
    int tid = threadIdx.x;
    int m0 = blockIdx.x * 128;

    if (tid < 128) {
        int row = m0 + tid;
        float s0 = 0.f, s1 = 0.f, s2 = 0.f, s3 = 0.f;
        if (row < NN) {
            s0 = g_scores[(size_t)row * 4 + 0];
            s1 = g_scores[(size_t)row * 4 + 1];
            s2 = g_scores[(size_t)row * 4 + 2];
            s3 = g_scores[(size_t)row * 4 + 3];
        }
        float mx = fmaxf(fmaxf(s0, s1), fmaxf(s2, s3));
        float e0 = expf(s0 - mx), e1 = expf(s1 - mx), e2 = expf(s2 - mx), e3 = expf(s3 - mx);
        float inv = 1.0f / (e0 + e1 + e2 + e3);
        sal[tid][0] = e0 * inv; sal[tid][1] = e1 * inv;
        sal[tid][2] = e2 * inv; sal[tid][3] = e3 * inv;
    }
    for (int i = tid; i < 128 * 40; i += 256) Ws[i / 40][i % 40] = Wout[i];
    __syncthreads();

    float acc[4][5];
#pragma unroll
    for (int r = 0; r < 4; ++r)
#pragma unroll
        for (int j = 0; j < 5; ++j) acc[r][j] = 0.f;

    int ty = tid >> 3, tx = tid & 7;
    const size_t LSTR = (size_t)NN * CDIM;

    for (int kc = 0; kc < 128; kc += 32) {
#pragma unroll
        for (int it = 0; it < 4; ++it) {
            int idx = it * 256 + tid;
            int m = idx >> 3, kq = idx & 7;
            int row = m0 + m;
            float4 v = make_float4(0.f, 0.f, 0.f, 0.f);
            if (row < NN) {
                size_t off = (size_t)row * 128 + kc + kq * 4;
                float a0 = sal[m][0], a1 = sal[m][1], a2 = sal[m][2], a3 = sal[m][3];
                float4 h0 = *(const float4*)(g_H + off);
                float4 h1 = *(const float4*)(g_H + off + LSTR);
                float4 h2 = *(const float4*)(g_H + off + 2 * LSTR);
                float4 h3 = *(const float4*)(g_H + off + 3 * LSTR);
                v.x = a0 * h0.x + a1 * h1.x + a2 * h2.x + a3 * h3.x;
                v.y = a0 * h0.y + a1 * h1.y + a2 * h2.y + a3 * h3.y;
                v.z = a0 * h0.z + a1 * h1.z + a2 * h2.z + a3 * h3.z;
                v.w = a0 * h0.w + a1 * h1.w + a2 * h2.w + a3 * h3.w;
            }
            At[m][kq * 4 + 0] = v.x; At[m][kq * 4 + 1] = v.y;
            At[m][kq * 4 + 2] = v.z; At[m][kq * 4 + 3] = v.w;
        }
        __syncthreads();
#pragma unroll
        for (int kk = 0; kk < 32; ++kk) {
            float a[4];
#pragma unroll
            for (int rr = 0; rr < 4; ++rr) a[rr] = At[ty * 4 + rr][kk];
            float b[5];
#pragma unroll
            for (int j = 0; j < 5; ++j) b[j] = Ws[kc + kk][tx * 5 + j];
#pragma unroll
            for (int rr = 0; rr < 4; ++rr)
#pragma unroll
                for (int j = 0; j < 5; ++j) acc[rr][j] += a[rr] * b[j];
        }
        __syncthreads();
    }

#pragma unroll
    for (int rr = 0; rr < 4; ++rr) {
        int row = m0 + ty * 4 + rr;
        if (row < NN) {
#pragma unroll
            for (int j = 0; j < 5; ++j) {
                int col = tx * 5 + j;
                out[(size_t)row * NCLASS + col] = acc[rr][j] + bout[col];
            }
        }
    }
}

// ---------------- launch ----------------
static const void* find_by_size(void* const* d_in, const int* in_sizes, int n_in,
                                long long want, const void* fallback) {
    for (int i = 0; i < n_in; ++i)
        if ((long long)in_sizes[i] == want) return d_in[i];
    return fallback;
}

extern "C" void kernel_launch(void* const* d_in, const int* in_sizes, int n_in,
                              void* d_out, int out_size) {
    const float* x     = (const float*)find_by_size(d_in, in_sizes, n_in, (long long)NN * CDIM, d_in[0]);
    const void*  ei    =               find_by_size(d_in, in_sizes, n_in, 2LL * NE,            d_in[1]);
    const float* convW = (const float*)find_by_size(d_in, in_sizes, n_in, (long long)NLAYER * CDIM * CDIM, d_in[2]);
    const float* convb = (const float*)find_by_size(d_in, in_sizes, n_in, (long long)NLAYER * CDIM, d_in[3]);
    const float* W_att = (const float*)find_by_size(d_in, in_sizes, n_in, (long long)CDIM * CDIM, d_in[4]);
    const float* a_att = (const float*)find_by_size(d_in, in_sizes, n_in, (long long)CDIM, d_in[5]);
    const float* W_out = (const float*)find_by_size(d_in, in_sizes, n_in, (long long)CDIM * NCLASS, d_in[6]);
    const float* b_out = (const float*)find_by_size(d_in, in_sizes, n_in, (long long)NCLASS, d_in[7]);
    float*       out   = (float*)d_out;

    zero_kernel<<<(NN + 255) / 256, 256>>>(ei);
    hist_kernel<<<(NE + 255) / 256, 256>>>(ei);
    scan1_kernel<<<49, 1024>>>();
    scan3_kernel<<<49, 1024>>>();
    scatter_kernel<<<(NE + 255) / 256, 256>>>(ei);
    bprep_kernel<<<(5 * 8192 + 255) / 256, 256>>>(convW, W_att);

    const int GB = (NN + 127) / 128;  // 391
    // layer 0: conv only (A = x)
    gemm_kernel<<<GB, 256>>>(x, a_att, -1, 0, 0, GB);
    agg_kernel<<<(NN * 32 + 255) / 256, 256>>>(convb, 0);
    // layers 1..3: fused conv(l) + att(l-1), both reading g_H[l-1]
    for (int l = 1; l < NLAYER; ++l) {
        gemm_kernel<<<2 * GB, 256>>>(x, a_att, l - 1, l, l - 1, GB);
        agg_kernel<<<(NN * 32 + 255) / 256, 256>>>(convb, l);
    }
    // att for the last layer
    gemm_kernel<<<GB, 256>>>(x, a_att, 3, 0, 3, 0);
    final_kernel<<<GB, 256>>>(W_out, b_out, out);
}

// round 16
// speedup vs baseline: 1.0906x; 1.0280x over previous
#include <cuda_runtime.h>
#include <cuda_bf16.h>
#include <cuda_fp16.h>
#include <math.h>

#define NN 50000
#define NE 800000
#define CDIM 128
#define NLAYER 4
#define NCLASS 40

// ---------------- scratch (device globals; no allocation allowed) ----------------
__device__ int   g_is64;
__device__ int   g_deg[NN];
__device__ int   g_fill[NN];
__device__ int   g_rowptr[NN + 1];
__device__ float g_dinv[NN];
__device__ int   g_bsum[64];
__device__ __align__(16) int2 g_cew[NE];                    // (src, bitcast ew) per edge
__device__ __align__(16) unsigned g_hWh[(size_t)NN * 64];   // hW rows as half2 (128 halves/row)
__device__ __align__(16) float g_H[(size_t)NLAYER * NN * CDIM];
__device__ __align__(16) float g_scores[(size_t)NN * NLAYER];
// pre-split weights: slot 0..3 = convW layers, slot 4 = W_att; [n][k] bf16x2 u32
__device__ __align__(16) unsigned g_Bh[5 * 128 * 64];
__device__ __align__(16) unsigned g_Bl[5 * 128 * 64];

// ---------------- helpers ----------------
__device__ __forceinline__ unsigned short bf_hi(float x) {
    return __bfloat16_as_ushort(__float2bfloat16(x));
}
__device__ __forceinline__ void split2(float x0, float x1, unsigned& hi, unsigned& lo) {
    unsigned short h0 = bf_hi(x0), h1 = bf_hi(x1);
    float r0 = x0 - __bfloat162float(__ushort_as_bfloat16(h0));
    float r1 = x1 - __bfloat162float(__ushort_as_bfloat16(h1));
    unsigned short l0 = bf_hi(r0), l1 = bf_hi(r1);
    hi = ((unsigned)h1 << 16) | h0;
    lo = ((unsigned)l1 << 16) | l0;
}
__device__ __forceinline__ void mma16816(float& c0, float& c1, float& c2, float& c3,
                                         unsigned a0, unsigned a1, unsigned a2, unsigned a3,
                                         unsigned b0, unsigned b1) {
    asm volatile("mma.sync.aligned.m16n8k16.row.col.f32.bf16.bf16.f32 "
                 "{%0,%1,%2,%3}, {%4,%5,%6,%7}, {%8,%9}, {%0,%1,%2,%3};"
                 : "+f"(c0), "+f"(c1), "+f"(c2), "+f"(c3)
                 : "r"(a0), "r"(a1), "r"(a2), "r"(a3), "r"(b0), "r"(b1));
}
__device__ __forceinline__ unsigned smem_u32(const void* p) {
    unsigned a;
    asm("{ .reg .u64 t; cvta.to.shared.u64 t, %1; cvt.u32.u64 %0, t; }" : "=r"(a) : "l"(p));
    return a;
}
__device__ __forceinline__ void ldsm_x4(unsigned& r0, unsigned& r1, unsigned& r2, unsigned& r3,
                                        unsigned addr) {
    asm volatile("ldmatrix.sync.aligned.m8n8.x4.shared.b16 {%0,%1,%2,%3}, [%4];"
                 : "=r"(r0), "=r"(r1), "=r"(r2), "=r"(r3) : "r"(addr));
}
__device__ __forceinline__ float tanh_fast(float x) {
    float y;
    asm("tanh.approx.f32 %0, %1;" : "=f"(y) : "f"(x));
    return y;
}

// ---------------- edge accessors ----------------
__device__ __forceinline__ int edge_src(const void* ei, int e) {
    return g_is64 ? (int)((const long long*)ei)[e] : ((const int*)ei)[e];
}
__device__ __forceinline__ int edge_dst(const void* ei, int e) {
    return g_is64 ? (int)((const long long*)ei)[NE + e] : ((const int*)ei)[NE + e];
}

// ---------------- CSR build ----------------
__global__ void zero_kernel(const void* ei) {
    int i = blockIdx.x * blockDim.x + threadIdx.x;
    if (i == 0) {
        const long long* p = (const long long*)ei;
        int ok = 1;
        for (int k = 0; k < 8; ++k) {
            long long v = p[k];
            if (v < 0 || v >= NN) ok = 0;
        }
        g_is64 = ok;
    }
    if (i < NN) { g_deg[i] = 0; g_fill[i] = 0; }
}
__global__ void hist_kernel(const void* __restrict__ ei) {
    int e = blockIdx.x * blockDim.x + threadIdx.x;
    if (e < NE) {
        int d = edge_dst(ei, e);
        if ((unsigned)d < NN) atomicAdd(&g_deg[d], 1);
    }
}
__global__ __launch_bounds__(1024) void scan1_kernel() {
    __shared__ int wsum[32];
    int b = blockIdx.x, t = threadIdx.x;
    int i = b * 1024 + t;
    int lane = t & 31, wid = t >> 5;
    int v = (i < NN) ? g_deg[i] : 0;
    if (i < NN) g_dinv[i] = rsqrtf(1.0f + (float)v);
    int inc = v;
#pragma unroll
    for (int o = 1; o < 32; o <<= 1) {
        int u = __shfl_up_sync(0xffffffffu, inc, o);
        if (lane >= o) inc += u;
    }
    if (lane == 31) wsum[wid] = inc;
    __syncthreads();
    if (wid == 0) {
        int s = wsum[lane];
#pragma unroll
        for (int o = 1; o < 32; o <<= 1) {
            int u = __shfl_up_sync(0xffffffffu, s, o);
            if (lane >= o) s += u;
        }
        wsum[lane] = s;
    }
    __syncthreads();
    int incl = inc + (wid ? wsum[wid - 1] : 0);
    if (i < NN) g_rowptr[i + 1] = incl;
    if (t == 1023) g_bsum[b] = incl;
}
__global__ __launch_bounds__(1024) void scan3_kernel() {
    __shared__ int sm[64];
    int b = blockIdx.x, t = threadIdx.x;
    if (t < 64) sm[t] = (t < 49) ? g_bsum[t] : 0;
    __syncthreads();
    for (int o = 1; o < 64; o <<= 1) {
        int u = (t < 64 && t >= o) ? sm[t - o] : 0;
        __syncthreads();
        if (t < 64) sm[t] += u;
        __syncthreads();
    }
    int add = (b == 0) ? 0 : sm[b - 1];
    int i = b * 1024 + t;
    if (i < NN) g_rowptr[i + 1] += add;
    if (i == 0) g_rowptr[0] = 0;
}
__global__ void scatter_kernel(const void* __restrict__ ei) {
    int e = blockIdx.x * blockDim.x + threadIdx.x;
    if (e < NE) {
        int s = edge_src(ei, e);
        int d = edge_dst(ei, e);
        if ((unsigned)s < NN && (unsigned)d < NN) {
            int pos = g_rowptr[d] + atomicAdd(&g_fill[d], 1);
            g_cew[pos] = make_int2(s, __float_as_int(g_dinv[s] * g_dinv[d]));
        }
    }
}

// ---------------- B prep: all 5 weight matrices at once ----------------
__global__ void bprep_kernel(const float* __restrict__ convW, const float* __restrict__ Watt) {
    int idx = blockIdx.x * 256 + threadIdx.x;
    if (idx >= 5 * 128 * 64) return;
    int slot = idx >> 13;          // 0..4
    int r = idx & 8191;
    int n = r >> 6, q = r & 63, k = q * 2;
    const float* B = (slot < 4) ? (convW + (size_t)slot * 128 * 128) : Watt;
    float x0 = B[(size_t)k * 128 + n];
    float x1 = B[(size_t)(k + 1) * 128 + n];
    unsigned hi, lo;
    split2(x0, x1, hi, lo);
    g_Bh[slot * 8192 + n * 64 + q] = hi;
    g_Bl[slot * 8192 + n * 64 + q] = lo;
}

// ---------------- tensor-core GEMM (split bf16), dual-role launch ----------------
// Blocks [0, nconv): conv  A @ convW[conv_slot] -> g_hWh (fp16)
// Blocks [nconv, grid): att  tanh(A @ W_att) . avec -> g_scores[:, att_layer]
// A = (a_layer < 0 ? x : g_H[a_layer]); both roles read the SAME A.
__global__ __launch_bounds__(256, 2) void gemm_kernel(const float* __restrict__ x,
                                                      const float* __restrict__ avec,
                                                      int a_layer, int conv_slot,
                                                      int att_layer, int nconv) {
    __shared__ unsigned short Ah[128][40], Al[128][40];   // row stride 80B = 16*5
    __shared__ unsigned short Bh[128][40], Bl[128][40];
    __shared__ float red[128][2];

    bool is_att = ((int)blockIdx.x >= nconv);
    int blk = is_att ? (int)blockIdx.x - nconv : (int)blockIdx.x;
    const float* A = (a_layer < 0) ? x : (g_H + (size_t)a_layer * NN * CDIM);
    int slot = is_att ? 4 : conv_slot;
    const unsigned* GBh = g_Bh + slot * 8192;
    const unsigned* GBl = g_Bl + slot * 8192;

    int tid = threadIdx.x;
    int m0 = blk * 128;
    int lane = tid & 31, w = tid >> 5;
    int g = lane >> 2, t = lane & 3;
    int wm = (w & 3) * 32, wn = (w >> 2) * 64;

    int mi = lane >> 3, r8 = lane & 7;
    unsigned a_h[2], a_l[2];
#pragma unroll
    for (int s = 0; s < 2; ++s) {
        int row = wm + s * 16 + (mi & 1) * 8 + r8;
        int col = (mi >> 1) * 8;
        a_h[s] = smem_u32(&Ah[row][col]);
        a_l[s] = smem_u32(&Al[row][col]);
    }
    unsigned b_h[4], b_l[4];
#pragma unroll
    for (int jp = 0; jp < 4; ++jp) {
        int row = wn + jp * 16 + (mi >> 1) * 8 + r8;
        int col = (mi & 1) * 8;
        b_h[jp] = smem_u32(&Bh[row][col]);
        b_l[jp] = smem_u32(&Bl[row][col]);
    }

    float c[2][8][4];
#pragma unroll
    for (int s = 0; s < 2; ++s)
#pragma unroll
        for (int j = 0; j < 8; ++j)
#pragma unroll
            for (int q = 0; q < 4; ++q) c[s][j][q] = 0.f;

    float4 pf[4];
#pragma unroll
    for (int it = 0; it < 4; ++it) {
        int idx = it * 256 + tid;
        int m = idx >> 3, q = idx & 7;
        int row = m0 + m;
        pf[it] = make_float4(0.f, 0.f, 0.f, 0.f);
        if (row < NN) pf[it] = *(const float4*)(A + (size_t)row * 128 + q * 4);
    }

    for (int kc = 0; kc < 128; kc += 32) {
        // store prefetched A (split)
#pragma unroll
        for (int it = 0; it < 4; ++it) {
            int idx = it * 256 + tid;
            int m = idx >> 3, q = idx & 7;
            unsigned h0, l0, h1, l1;
            split2(pf[it].x, pf[it].y, h0, l0);
            split2(pf[it].z, pf[it].w, h1, l1);
            *(unsigned*)&Ah[m][q * 4]     = h0;
            *(unsigned*)&Ah[m][q * 4 + 2] = h1;
            *(unsigned*)&Al[m][q * 4]     = l0;
            *(unsigned*)&Al[m][q * 4 + 2] = l1;
        }
        // stage B chunk: vectorized uint4 (1024 uint4 = 512 hi + 512 lo)
#pragma unroll
        for (int it = 0; it < 4; ++it) {
            int idx = it * 256 + tid;
            int half = idx >> 9;               // 0: hi, 1: lo
            int rr = idx & 511;
            int n = rr >> 2, q4 = rr & 3;      // q4: uint4 within the row chunk
            uint4 val = *(const uint4*)((half ? GBl : GBh) + n * 64 + (kc >> 1) + q4 * 4);
            if (half) *(uint4*)&Bl[n][q4 * 8] = val;
            else      *(uint4*)&Bh[n][q4 * 8] = val;
        }
        __syncthreads();

        if (kc < 96) {
#pragma unroll
            for (int it = 0; it < 4; ++it) {
                int idx = it * 256 + tid;
                int m = idx >> 3, q = idx & 7;
                int row = m0 + m;
                pf[it] = make_float4(0.f, 0.f, 0.f, 0.f);
                if (row < NN) pf[it] = *(const float4*)(A + (size_t)row * 128 + kc + 32 + q * 4);
            }
        }

#pragma unroll
        for (int ks = 0; ks < 32; ks += 16) {
            unsigned koff = ks * 2;
            unsigned ah[2][4], al[2][4];
#pragma unroll
            for (int s = 0; s < 2; ++s) {
                ldsm_x4(ah[s][0], ah[s][1], ah[s][2], ah[s][3], a_h[s] + koff);
                ldsm_x4(al[s][0], al[s][1], al[s][2], al[s][3], a_l[s] + koff);
            }
#pragma unroll
            for (int jp = 0; jp < 4; ++jp) {
                unsigned bh0, bh1, bh2, bh3, bl0, bl1, bl2, bl3;
                ldsm_x4(bh0, bh1, bh2, bh3, b_h[jp] + koff);
                ldsm_x4(bl0, bl1, bl2, bl3, b_l[jp] + koff);
#pragma unroll
                for (int s = 0; s < 2; ++s) {
                    mma16816(c[s][2 * jp][0], c[s][2 * jp][1], c[s][2 * jp][2], c[s][2 * jp][3],
                             ah[s][0], ah[s][1], ah[s][2], ah[s][3], bh0, bh1);
                    mma16816(c[s][2 * jp][0], c[s][2 * jp][1], c[s][2 * jp][2], c[s][2 * jp][3],
                             ah[s][0], ah[s][1], ah[s][2], ah[s][3], bl0, bl1);
                    mma16816(c[s][2 * jp][0], c[s][2 * jp][1], c[s][2 * jp][2], c[s][2 * jp][3],
                             al[s][0], al[s][1], al[s][2], al[s][3], bh0, bh1);
                    mma16816(c[s][2 * jp + 1][0], c[s][2 * jp + 1][1], c[s][2 * jp + 1][2], c[s][2 * jp + 1][3],
                             ah[s][0], ah[s][1], ah[s][2], ah[s][3], bh2, bh3);
                    mma16816(c[s][2 * jp + 1][0], c[s][2 * jp + 1][1], c[s][2 * jp + 1][2], c[s][2 * jp + 1][3],
                             ah[s][0], ah[s][1], ah[s][2], ah[s][3], bl2, bl3);
                    mma16816(c[s][2 * jp + 1][0], c[s][2 * jp + 1][1], c[s][2 * jp + 1][2], c[s][2 * jp + 1][3],
                             al[s][0], al[s][1], al[s][2], al[s][3], bh2, bh3);
                }
            }
        }
        __syncthreads();
    }

    if (!is_att) {
        __half2* C = (__half2*)g_hWh;
#pragma unroll
        for (int s = 0; s < 2; ++s) {
#pragma unroll
            for (int j = 0; j < 8; ++j) {
                int rr = m0 + wm + s * 16 + g;
                int n = wn + j * 8 + 2 * t;        // even
                if (rr < NN)     C[(size_t)rr * 64 + (n >> 1)]       = __floats2half2_rn(c[s][j][0], c[s][j][1]);
                if (rr + 8 < NN) C[(size_t)(rr + 8) * 64 + (n >> 1)] = __floats2half2_rn(c[s][j][2], c[s][j][3]);
            }
        }
    } else {
        float p[2][2] = {{0.f, 0.f}, {0.f, 0.f}};
#pragma unroll
        for (int j = 0; j < 8; ++j) {
            int n = wn + j * 8 + 2 * t;
            float a0 = avec[n], a1 = avec[n + 1];
#pragma unroll
            for (int s = 0; s < 2; ++s) {
                p[s][0] += tanh_fast(c[s][j][0]) * a0 + tanh_fast(c[s][j][1]) * a1;
                p[s][1] += tanh_fast(c[s][j][2]) * a0 + tanh_fast(c[s][j][3]) * a1;
            }
        }
#pragma unroll
        for (int s = 0; s < 2; ++s)
#pragma unroll
            for (int h = 0; h < 2; ++h) {
                p[s][h] += __shfl_xor_sync(0xffffffffu, p[s][h], 1);
                p[s][h] += __shfl_xor_sync(0xffffffffu, p[s][h], 2);
            }
        __syncthreads();
        if (t == 0) {
#pragma unroll
            for (int s = 0; s < 2; ++s) {
                red[wm + s * 16 + g][w >> 2]     = p[s][0];
                red[wm + s * 16 + g + 8][w >> 2] = p[s][1];
            }
        }
        __syncthreads();
        if (tid < 128) {
            int row = m0 + tid;
            if (row < NN)
                g_scores[(size_t)row * NLAYER + att_layer] = red[tid][0] + red[tid][1];
        }
    }
}

// ---------------- aggregation: one warp per dst node, fp16 gather, 4-edge MLP ----------------
__global__ __launch_bounds__(256) void agg_kernel(const float* __restrict__ convb, int l) {
    int w = (blockIdx.x * blockDim.x + threadIdx.x) >> 5;
    int lane = threadIdx.x & 31;
    if (w >= NN) return;
    const float* bias = convb + (size_t)l * CDIM;
    const uint2* hw = (const uint2*)g_hWh;
    const int2* cew = g_cew;
    float4 acc = make_float4(0.f, 0.f, 0.f, 0.f);
    int e = g_rowptr[w], e1 = g_rowptr[w + 1];

    for (; e + 3 < e1; e += 4) {
        int2 c0 = cew[e], c1 = cew[e + 1], c2 = cew[e + 2], c3 = cew[e + 3];
        uint2 u0 = hw[(size_t)c0.x * 32 + lane];
        uint2 u1 = hw[(size_t)c1.x * 32 + lane];
        uint2 u2 = hw[(size_t)c2.x * 32 + lane];
        uint2 u3 = hw[(size_t)c3.x * 32 + lane];
        float w0 = __int_as_float(c0.y), w1 = __int_as_float(c1.y);
        float w2 = __int_as_float(c2.y), w3 = __int_as_float(c3.y);
        float2 a0 = __half22float2(*(__half2*)&u0.x), b0 = __half22float2(*(__half2*)&u0.y);
        float2 a1 = __half22float2(*(__half2*)&u1.x), b1 = __half22float2(*(__half2*)&u1.y);
        float2 a2 = __half22float2(*(__half2*)&u2.x), b2 = __half22float2(*(__half2*)&u2.y);
        float2 a3 = __half22float2(*(__half2*)&u3.x), b3 = __half22float2(*(__half2*)&u3.y);
        acc.x += w0 * a0.x + w1 * a1.x + w2 * a2.x + w3 * a3.x;
        acc.y += w0 * a0.y + w1 * a1.y + w2 * a2.y + w3 * a3.y;
        acc.z += w0 * b0.x + w1 * b1.x + w2 * b2.x + w3 * b3.x;
        acc.w += w0 * b0.y + w1 * b1.y + w2 * b2.y + w3 * b3.y;
    }
    if (e + 1 < e1) {
        int2 c0 = cew[e], c1 = cew[e + 1];
        uint2 u0 = hw[(size_t)c0.x * 32 + lane];
        uint2 u1 = hw[(size_t)c1.x * 32 + lane];
        float w0 = __int_as_float(c0.y), w1 = __int_as_float(c1.y);
        float2 a0 = __half22float2(*(__half2*)&u0.x), b0 = __half22float2(*(__half2*)&u0.y);
        float2 a1 = __half22float2(*(__half2*)&u1.x), b1 = __half22float2(*(__half2*)&u1.y);
        acc.x += w0 * a0.x + w1 * a1.x;
        acc.y += w0 * a0.y + w1 * a1.y;
        acc.z += w0 * b0.x + w1 * b1.x;
        acc.w += w0 * b0.y + w1 * b1.y;
        e += 2;
    }
    if (e < e1) {
        int2 c0 = cew[e];
        uint2 u0 = hw[(size_t)c0.x * 32 + lane];
        float w0 = __int_as_float(c0.y);
        float2 a0 = __half22float2(*(__half2*)&u0.x), b0 = __half22float2(*(__half2*)&u0.y);
        acc.x += w0 * a0.x; acc.y += w0 * a0.y;
        acc.z += w0 * b0.x; acc.w += w0 * b0.y;
    }
    float di = g_dinv[w];
    float sn = di * di;
    uint2 us = hw[(size_t)w * 32 + lane];
    float2 s0 = __half22float2(*(__half2*)&us.x), s1 = __half22float2(*(__half2*)&us.y);
    const float4* b4 = (const float4*)bias;
    float4 b = b4[lane];
    float4 r;
    r.x = fmaxf(acc.x + sn * s0.x + b.x, 0.f);
    r.y = fmaxf(acc.y + sn * s0.y + b.y, 0.f);
    r.z = fmaxf(acc.z + sn * s1.x + b.z, 0.f);
    r.w = fmaxf(acc.w + sn * s1.y + b.w, 0.f);
    ((float4*)(g_H + (size_t)l * NN * CDIM))[(size_t)w * 32 + lane] = r;
}

// ---------------- final: softmax over layers + layer-mix + out GEMM ----------------
__global__ __launch_bounds__(256) void final_kernel(const float* __restrict__ Wout,
                                                    const float* __restrict__ bout,
                                                    float* __restrict__ out) {
    __shared__ float At[128][33];
    __shared__ float Ws[128][40];
    __shared__ float sal[128][4];
    int tid = threadIdx.x;
    int m0 = blockIdx.x * 128;

    if (tid < 128) {
        int row = m0 + tid;
        float s0 = 0.f, s1 = 0.f, s2 = 0.f, s3 = 0.f;
        if (row < NN) {
            s0 = g_scores[(size_t)row * 4 + 0];
            s1 = g_scores[(size_t)row * 4 + 1];
            s2 = g_scores[(size_t)row * 4 + 2];
            s3 = g_scores[(size_t)row * 4 + 3];
        }
        float mx = fmaxf(fmaxf(s0, s1), fmaxf(s2, s3));
        float e0 = expf(s0 - mx), e1 = expf(s1 - mx), e2 = expf(s2 - mx), e3 = expf(s3 - mx);
        float inv = 1.0f / (e0 + e1 + e2 + e3);
        sal[tid][0] = e0 * inv; sal[tid][1] = e1 * inv;
        sal[tid][2] = e2 * inv; sal[tid][3] = e3 * inv;
    }
    for (int i = tid; i < 128 * 40; i += 256) Ws[i / 40][i % 40] = Wout[i];
    __syncthreads();

    float acc[4][5];
#pragma unroll
    for (int r = 0; r < 4; ++r)
#pragma unroll
        for (int j = 0; j < 5; ++j) acc[r][j] = 0.f;

    int ty = tid >> 3, tx = tid & 7;
    const size_t LSTR = (size_t)NN * CDIM;

    for (int kc = 0; kc < 128; kc += 32) {
#pragma unroll
        for (int it = 0; it < 4; ++it) {
            int idx = it * 256 + tid;
            int m = idx >> 3, kq = idx & 7;
            int row = m0 + m;
            float4 v = make_float4(0.f, 0.f, 0.f, 0.f);
            if (row < NN) {
                size_t off = (size_t)row * 128 + kc + kq * 4;
                float a0 = sal[m][0], a1 = sal[m][1], a2 = sal[m][2], a3 = sal[m][3];
                float4 h0 = *(const float4*)(g_H + off);
                float4 h1 = *(const float4*)(g_H + off + LSTR);
                float4 h2 = *(const float4*)(g_H + off + 2 * LSTR);
                float4 h3 = *(const float4*)(g_H + off + 3 * LSTR);
                v.x = a0 * h0.x + a1 * h1.x + a2 * h2.x + a3 * h3.x;
                v.y = a0 * h0.y + a1 * h1.y + a2 * h2.y + a3 * h3.y;
                v.z = a0 * h0.z + a1 * h1.z + a2 * h2.z + a3 * h3.z;
                v.w = a0 * h0.w + a1 * h1.w + a2 * h2.w + a3 * h3.w;
            }
            At[m][kq * 4 + 0] = v.x; At[m][kq * 4 + 1] = v.y;
            At[m][kq * 4 + 2] = v.z; At[m][kq * 4 + 3] = v.w;
        }
        __syncthreads();
#pragma unroll
        for (int kk = 0; kk < 32; ++kk) {
            float a[4];
#pragma unroll
            for (int rr = 0; rr < 4; ++rr) a[rr] = At[ty * 4 + rr][kk];
            float b[5];
#pragma unroll
            for (int j = 0; j < 5; ++j) b[j] = Ws[kc + kk][tx * 5 + j];
#pragma unroll
            for (int rr = 0; rr < 4; ++rr)
#pragma unroll
                for (int j = 0; j < 5; ++j) acc[rr][j] += a[rr] * b[j];
        }
        __syncthreads();
    }

#pragma unroll
    for (int rr = 0; rr < 4; ++rr) {
        int row = m0 + ty * 4 + rr;
        if (row < NN) {
#pragma unroll
            for (int j = 0; j < 5; ++j) {
                int col = tx * 5 + j;
                out[(size_t)row * NCLASS + col] = acc[rr][j] + bout[col];
            }
        }
    }
}

// ---------------- launch ----------------
static const void* find_by_size(void* const* d_in, const int* in_sizes, int n_in,
                                long long want, const void* fallback) {
    for (int i = 0; i < n_in; ++i)
        if ((long long)in_sizes[i] == want) return d_in[i];
    return fallback;
}

extern "C" void kernel_launch(void* const* d_in, const int* in_sizes, int n_in,
                              void* d_out, int out_size) {
    const float* x     = (const float*)find_by_size(d_in, in_sizes, n_in, (long long)NN * CDIM, d_in[0]);
    const void*  ei    =               find_by_size(d_in, in_sizes, n_in, 2LL * NE,            d_in[1]);
    const float* convW = (const float*)find_by_size(d_in, in_sizes, n_in, (long long)NLAYER * CDIM * CDIM, d_in[2]);
    const float* convb = (const float*)find_by_size(d_in, in_sizes, n_in, (long long)NLAYER * CDIM, d_in[3]);
    const float* W_att = (const float*)find_by_size(d_in, in_sizes, n_in, (long long)CDIM * CDIM, d_in[4]);
    const float* a_att = (const float*)find_by_size(d_in, in_sizes, n_in, (long long)CDIM, d_in[5]);
    const float* W_out = (const float*)find_by_size(d_in, in_sizes, n_in, (long long)CDIM * NCLASS, d_in[6]);
    const float* b_out = (const float*)find_by_size(d_in, in_sizes, n_in, (long long)NCLASS, d_in[7]);
    float*       out   = (float*)d_out;

    // side stream for the CSR chain (low-occupancy serial kernels); overlaps with
    // bprep + conv(0) on the capture stream. Host handles are created per call.
    cudaStream_t s2;
    cudaStreamCreateWithFlags(&s2, cudaStreamNonBlocking);
    cudaEvent_t evFork, evCsr;
    cudaEventCreateWithFlags(&evFork, cudaEventDisableTiming);
    cudaEventCreateWithFlags(&evCsr, cudaEventDisableTiming);

    // fork: s2 starts after capture-stream origin
    cudaEventRecord(evFork, 0);
    cudaStreamWaitEvent(s2, evFork, 0);

    // side: CSR build chain
    zero_kernel<<<(NN + 255) / 256, 256, 0, s2>>>(ei);
    hist_kernel<<<(NE + 255) / 256, 256, 0, s2>>>(ei);
    scan1_kernel<<<49, 1024, 0, s2>>>();
    scan3_kernel<<<49, 1024, 0, s2>>>();
    scatter_kernel<<<(NE + 255) / 256, 256, 0, s2>>>(ei);
    cudaEventRecord(evCsr, s2);

    // main: weight prep + layer-0 conv GEMM (independent of CSR)
    bprep_kernel<<<(5 * 8192 + 255) / 256, 256>>>(convW, W_att);
    const int GB = (NN + 127) / 128;  // 391
    gemm_kernel<<<GB, 256>>>(x, a_att, -1, 0, 0, GB);

    // join: agg(0) needs scatter + conv(0)
    cudaStreamWaitEvent(0, evCsr, 0);
    agg_kernel<<<(NN * 32 + 255) / 256, 256>>>(convb, 0);

    // layers 1..3: fused conv(l) + att(l-1), both reading g_H[l-1]
    for (int l = 1; l < NLAYER; ++l) {
        gemm_kernel<<<2 * GB, 256>>>(x, a_att, l - 1, l, l - 1, GB);
        agg_kernel<<<(NN * 32 + 255) / 256, 256>>>(convb, l);
    }
    // att for the last layer
    gemm_kernel<<<GB, 256>>>(x, a_att, 3, 0, 3, 0);
    final_kernel<<<GB, 256>>>(W_out, b_out, out);
}